// round 1
// baseline (speedup 1.0000x reference)
#include <cuda_runtime.h>
#include <cuda_bf16.h>
#include <math.h>

// Problem constants
#define NV 5
#define NB_ 32      // batch
#define NP 20
#define NJ 17
#define NBONES 16
#define ND 128
#define HR 1024
#define HID 1024
#define NROWS (NB_*NP)          // 640
#define NC (NJ + NBONES)        // 33
#define WROW 104                // padded weight row (99 Wc1 + bc1 + 3 Wc2 + pad)

// Scratch (device globals; no runtime allocation)
__device__ float g_rough[NROWS * NJ];
__device__ float g_xin[NROWS * NC * ND];          // (n, c, t)
__device__ float g_Wp[HID * WROW];

// ---------------------------------------------------------------------------
// Kernel A: rough depth MLP.  One block per (b,p).
// ---------------------------------------------------------------------------
__global__ __launch_bounds__(128) void k_rough(
    const float* __restrict__ kpts, const float* __restrict__ image_wh,
    const float* __restrict__ Wr1, const float* __restrict__ br1,
    const float* __restrict__ Wr2, const float* __restrict__ br2)
{
    __shared__ float xs[NJ * 2];
    __shared__ float hs[HR];
    const int n = blockIdx.x;
    const int b = n / NP, p = n % NP;
    const int tid = threadIdx.x;

    if (tid < NJ * 2) {
        int c = tid & 1;
        float wh = image_wh[c];  // view 0, batch 0
        xs[tid] = kpts[(((0 * NB_ + b) * NP + p) * NJ) * 2 + tid] / wh;
    }
    __syncthreads();

    for (int i = tid; i < HR; i += 128) {
        const float* wr = Wr1 + i * (NJ * 2);
        float acc = br1[i];
        #pragma unroll
        for (int m = 0; m < NJ * 2; ++m) acc += wr[m] * xs[m];
        hs[i] = fmaxf(acc, 0.0f);
    }
    __syncthreads();

    const int warp = tid >> 5, lane = tid & 31;
    for (int j = warp; j < NJ; j += 4) {
        const float* wr = Wr2 + j * HR;
        float acc = 0.0f;
        for (int i = lane; i < HR; i += 32) acc += hs[i] * wr[i];
        #pragma unroll
        for (int off = 16; off > 0; off >>= 1)
            acc += __shfl_down_sync(0xffffffffu, acc, off);
        if (lane == 0) g_rough[n * NJ + j] = (acc + br2[j]) * 1000.0f;
    }
}

// ---------------------------------------------------------------------------
// Kernel W: repack conv weights into 16B-aligned 104-float rows.
// row h: [0..98]=Wc1[h], [99]=bc1[h], [100..102]=Wc2[0][h][:], [103]=0
// ---------------------------------------------------------------------------
__global__ void k_repack(const float* __restrict__ Wc1,
                         const float* __restrict__ bc1,
                         const float* __restrict__ Wc2)
{
    const int h = blockIdx.x;
    const int t = threadIdx.x;
    if (t >= WROW) return;
    float v;
    if (t < 99)        v = Wc1[h * 99 + t];
    else if (t == 99)  v = bc1[h];
    else if (t < 103)  v = Wc2[h * 3 + (t - 100)];
    else               v = 0.0f;
    g_Wp[h * WROW + t] = v;
}

// ---------------------------------------------------------------------------
// Kernel B: projection + person matching + scores for all 4 ref views.
// One block per (b,p); thread = depth bin d.
// ---------------------------------------------------------------------------
__global__ __launch_bounds__(128) void k_match(
    const float* __restrict__ kpts, const float* __restrict__ joint_vis,
    const float* __restrict__ cam_R, const float* __restrict__ cam_T,
    const float* __restrict__ cam_f, const float* __restrict__ cam_c,
    const float* __restrict__ image_wh, const int* __restrict__ num_persons,
    const int* __restrict__ bones)
{
    __shared__ float s_pr[NP * NJ * 2];
    __shared__ float s_vr[NP * NJ];
    __shared__ float s_rough[NJ];
    __shared__ float s_uvn[NJ * 2];
    __shared__ float s_R0[9], s_T0[3];
    __shared__ float s_Rr[9], s_Tr[3], s_fr[2], s_cr[2], s_wh[2];
    __shared__ int   s_bones[NBONES * 2];
    __shared__ float s_p2t[128 * 35];   // per-thread row of 17 (x,y) pairs, padded

    const int n = blockIdx.x;
    const int b = n / NP, p = n % NP;
    const int d = threadIdx.x;

    if (d < NJ) s_rough[d] = g_rough[n * NJ + d];
    if (d < 9)  s_R0[d] = cam_R[(0 * NB_ + b) * 9 + d];
    if (d < 3)  s_T0[d] = cam_T[(0 * NB_ + b) * 3 + d];
    if (d >= 32 && d < 32 + NBONES * 2) s_bones[d - 32] = bones[d - 32];
    if (d >= 64 && d < 64 + NJ * 2) {
        int m = d - 64;
        int c = m & 1;
        float cc = cam_c[(0 * NB_ + b) * 2 + c];
        float ff = cam_f[(0 * NB_ + b) * 2 + c];
        s_uvn[m] = (kpts[(((0 * NB_ + b) * NP + p) * NJ) * 2 + m] - cc) / ff;
    }

    float sc[NJ], bd[NJ], sc2[NBONES], bd2[NBONES];
    #pragma unroll
    for (int j = 0; j < NJ; ++j) { sc[j] = 0.0f; bd[j] = 0.0f; }
    #pragma unroll
    for (int e = 0; e < NBONES; ++e) { sc2[e] = 0.0f; bd2[e] = 0.0f; }

    const float label = ((float)d / 127.0f) * 6000.0f + 2000.0f;

    for (int rv = 1; rv < NV; ++rv) {
        __syncthreads();   // protect shared reuse across view iterations
        const int cambase = rv * NB_ + b;
        {
            const float* src = kpts + (size_t)cambase * NP * NJ * 2;
            for (int idx = d; idx < NP * NJ * 2; idx += 128) s_pr[idx] = src[idx];
            const float* vsrc = joint_vis + (size_t)cambase * NP * NJ;
            for (int idx = d; idx < NP * NJ; idx += 128) s_vr[idx] = vsrc[idx];
            if (d < 9) s_Rr[d] = cam_R[cambase * 9 + d];
            if (d < 3) s_Tr[d] = cam_T[cambase * 3 + d];
            if (d < 2) {
                s_fr[d] = cam_f[cambase * 2 + d];
                s_cr[d] = cam_c[cambase * 2 + d];
                s_wh[d] = image_wh[cambase * 2 + d];
            }
        }
        __syncthreads();
        const int np_r = num_persons[rv * NB_ + b];

        float px[NJ], py[NJ];
        #pragma unroll
        for (int j = 0; j < NJ; ++j) {
            float z  = label + s_rough[j];
            float cx = s_uvn[2 * j] * z;
            float cy = s_uvn[2 * j + 1] * z;
            float p0 = s_R0[0] * cx + s_R0[3] * cy + s_R0[6] * z + s_T0[0];
            float p1 = s_R0[1] * cx + s_R0[4] * cy + s_R0[7] * z + s_T0[1];
            float p2 = s_R0[2] * cx + s_R0[5] * cy + s_R0[8] * z + s_T0[2];
            float q0 = p0 - s_Tr[0], q1 = p1 - s_Tr[1], q2 = p2 - s_Tr[2];
            float xc0 = s_Rr[0] * q0 + s_Rr[1] * q1 + s_Rr[2] * q2;
            float xc1 = s_Rr[3] * q0 + s_Rr[4] * q1 + s_Rr[5] * q2;
            float xc2 = s_Rr[6] * q0 + s_Rr[7] * q1 + s_Rr[8] * q2;
            float inv = 1.0f / (xc2 + 1e-8f);
            px[j] = xc0 * inv * s_fr[0] + s_cr[0];
            py[j] = xc1 * inv * s_fr[1] + s_cr[1];
            s_p2t[d * 35 + 2 * j]     = px[j];
            s_p2t[d * 35 + 2 * j + 1] = py[j];
        }

        // argmin over candidate persons (first-min semantics)
        float best = 3.4e38f; int mm = 0;
        for (int q = 0; q < NP; ++q) {
            float num = 0.0f, den = 0.0f;
            #pragma unroll
            for (int j = 0; j < NJ; ++j) {
                float w  = s_vr[q * NJ + j];
                float dx = px[j] - s_pr[(q * NJ + j) * 2];
                float dy = py[j] - s_pr[(q * NJ + j) * 2 + 1];
                num += w * (dx * dx + dy * dy);
                den += w;
            }
            float val = num / (den + 1e-8f);
            if (q >= np_r) val = 100000.0f;
            if (val < best) { best = val; mm = q; }
        }

        const int mbase = mm * NJ;
        #pragma unroll
        for (int j = 0; j < NJ; ++j) {
            float mx = s_pr[(mbase + j) * 2];
            float my = s_pr[(mbase + j) * 2 + 1];
            float mv = s_vr[mbase + j];
            float dx = px[j] - mx, dy = py[j] - my;
            float score = expf(-sqrtf(dx * dx + dy * dy + 1e-12f) * (1.0f / 100.0f));
            float inb = (px[j] >= 0.0f && py[j] >= 0.0f &&
                         px[j] <= s_wh[0] - 1.0f && py[j] <= s_wh[1] - 1.0f) ? 1.0f : 0.0f;
            float bnd = inb * mv;
            sc[j] += score * bnd;
            bd[j] += bnd;
        }

        const float b20 = s_vr[mbase + 0];
        #pragma unroll
        for (int e = 0; e < NBONES; ++e) {
            int a = s_bones[2 * e], bb = s_bones[2 * e + 1];
            float pax = s_p2t[d * 35 + 2 * a], pay = s_p2t[d * 35 + 2 * a + 1];
            float pbx = s_p2t[d * 35 + 2 * bb], pby = s_p2t[d * 35 + 2 * bb + 1];
            float dxp = pax - pbx, dyp = pay - pby;
            float blp = sqrtf(dxp * dxp + dyp * dyp + 1e-12f);
            float max_ = s_pr[(mbase + a) * 2],  may_ = s_pr[(mbase + a) * 2 + 1];
            float mbx_ = s_pr[(mbase + bb) * 2], mby_ = s_pr[(mbase + bb) * 2 + 1];
            float dxm = max_ - mbx_, dym = may_ - mby_;
            float blm = sqrtf(dxm * dxm + dym * dym + 1e-12f);
            float sbl = expf(-fabsf(blm - blp) * 0.2f);
            sc2[e] += sbl * b20;
            bd2[e] += b20;
        }
    }

    float* xrow = g_xin + (size_t)n * NC * ND;
    #pragma unroll
    for (int j = 0; j < NJ; ++j)
        xrow[j * ND + d] = sc[j] / (bd[j] + 1e-8f);
    #pragma unroll
    for (int e = 0; e < NBONES; ++e)
        xrow[(NJ + e) * ND + d] = sc2[e] / (bd2[e] + 1e-8f);
}

// ---------------------------------------------------------------------------
// Kernel C: conv1(33->1024,k3) + relu + conv2(1024->1,k3) + softmax +
// masked expectation.  One block (256 thr) per row n.
// Warp owns h-stripe (h = hi*8 + warp), lane owns t in [4l, 4l+4).
// ---------------------------------------------------------------------------
__global__ __launch_bounds__(256) void k_conv(
    const float* __restrict__ bc2, float* __restrict__ out)
{
    __shared__ __align__(16) float s_x[NC][132];
    __shared__ __align__(16) float s_w[8][WROW];
    __shared__ float s_logit[ND];
    __shared__ float s_red[ND];

    const int n = blockIdx.x;
    const int tid = threadIdx.x;
    const int w = tid >> 5, l = tid & 31;

    {
        const float* src = g_xin + (size_t)n * NC * ND;
        for (int idx = tid; idx < NC * ND; idx += 256) {
            int c = idx >> 7, t = idx & 127;
            s_x[c][t] = src[idx];
        }
        if (tid < ND) s_logit[tid] = bc2[0];
    }
    __syncthreads();

    float a0 = 0.0f, a1 = 0.0f, a2 = 0.0f, a3 = 0.0f;

    for (int hi = 0; hi < HID / 8; ++hi) {
        const int h = hi * 8 + w;
        __syncwarp();
        if (l < WROW / 4)
            *(float4*)&s_w[w][l * 4] = *(const float4*)&g_Wp[h * WROW + l * 4];
        __syncwarp();

        float y0 = s_w[w][99], y1 = y0, y2 = y0, y3 = y0;
        #pragma unroll
        for (int c = 0; c < NC; ++c) {
            float w0 = s_w[w][3 * c], w1 = s_w[w][3 * c + 1], w2 = s_w[w][3 * c + 2];
            float4 xv = *(const float4*)&s_x[c][l * 4];
            float xm1 = __shfl_up_sync(0xffffffffu, xv.w, 1);
            float xp4 = __shfl_down_sync(0xffffffffu, xv.x, 1);
            if (l == 0)  xm1 = 0.0f;
            if (l == 31) xp4 = 0.0f;
            y0 += w0 * xm1  + w1 * xv.x + w2 * xv.y;
            y1 += w0 * xv.x + w1 * xv.y + w2 * xv.z;
            y2 += w0 * xv.y + w1 * xv.z + w2 * xv.w;
            y3 += w0 * xv.z + w1 * xv.w + w2 * xp4;
        }
        y0 = fmaxf(y0, 0.0f); y1 = fmaxf(y1, 0.0f);
        y2 = fmaxf(y2, 0.0f); y3 = fmaxf(y3, 0.0f);

        float c0 = s_w[w][100], c1 = s_w[w][101], c2 = s_w[w][102];
        float ym1 = __shfl_up_sync(0xffffffffu, y3, 1);
        float yp4 = __shfl_down_sync(0xffffffffu, y0, 1);
        if (l == 0)  ym1 = 0.0f;
        if (l == 31) yp4 = 0.0f;
        a0 += c0 * ym1 + c1 * y0 + c2 * y1;
        a1 += c0 * y0  + c1 * y1 + c2 * y2;
        a2 += c0 * y1  + c1 * y2 + c2 * y3;
        a3 += c0 * y2  + c1 * y3 + c2 * yp4;
    }

    atomicAdd(&s_logit[4 * l + 0], a0);
    atomicAdd(&s_logit[4 * l + 1], a1);
    atomicAdd(&s_logit[4 * l + 2], a2);
    atomicAdd(&s_logit[4 * l + 3], a3);
    __syncthreads();

    // max
    if (tid < ND) s_red[tid] = s_logit[tid];
    __syncthreads();
    for (int s = 64; s > 0; s >>= 1) {
        if (tid < s) s_red[tid] = fmaxf(s_red[tid], s_red[tid + s]);
        __syncthreads();
    }
    const float mx = s_red[0];
    __syncthreads();

    // first argmax
    if (tid < ND) s_red[tid] = (s_logit[tid] == mx) ? (float)tid : 1.0e9f;
    __syncthreads();
    for (int s = 64; s > 0; s >>= 1) {
        if (tid < s) s_red[tid] = fminf(s_red[tid], s_red[tid + s]);
        __syncthreads();
    }
    const int idx = (int)s_red[0];
    __syncthreads();

    float e = 0.0f;
    if (tid < ND) e = expf(s_logit[tid] - mx);

    // S = sum(e)
    if (tid < ND) s_red[tid] = e;
    __syncthreads();
    for (int s = 64; s > 0; s >>= 1) {
        if (tid < s) s_red[tid] += s_red[tid + s];
        __syncthreads();
    }
    const float S = s_red[0];
    __syncthreads();

    const float me = (tid < ND && abs(tid - idx) <= 5) ? e : 0.0f;

    // den = sum(me)
    if (tid < ND) s_red[tid] = me;
    __syncthreads();
    for (int s = 64; s > 0; s >>= 1) {
        if (tid < s) s_red[tid] += s_red[tid + s];
        __syncthreads();
    }
    const float den = s_red[0];
    __syncthreads();

    // num = sum(me * t)
    if (tid < ND) s_red[tid] = me * (float)tid;
    __syncthreads();
    for (int s = 64; s > 0; s >>= 1) {
        if (tid < s) s_red[tid] += s_red[tid + s];
        __syncthreads();
    }
    if (tid == 0) {
        float pred = s_red[0] / (den + 1e-8f * S);
        out[n] = pred * (6000.0f / 127.0f) + 2000.0f;
    }
}

// ---------------------------------------------------------------------------
extern "C" void kernel_launch(void* const* d_in, const int* in_sizes, int n_in,
                              void* d_out, int out_size)
{
    const float* kpts        = (const float*)d_in[0];
    const float* joint_vis   = (const float*)d_in[2];
    const float* cam_R       = (const float*)d_in[5];
    const float* cam_T       = (const float*)d_in[6];
    const float* cam_f       = (const float*)d_in[7];
    const float* cam_c       = (const float*)d_in[8];
    const float* image_wh    = (const float*)d_in[9];
    const int*   num_persons = (const int*)d_in[10];
    const float* Wr1         = (const float*)d_in[11];
    const float* br1         = (const float*)d_in[12];
    const float* Wr2         = (const float*)d_in[13];
    const float* br2         = (const float*)d_in[14];
    const float* Wc1         = (const float*)d_in[15];
    const float* bc1         = (const float*)d_in[16];
    const float* Wc2         = (const float*)d_in[17];
    const float* bc2         = (const float*)d_in[18];
    const int*   bones       = (const int*)d_in[19];
    float* out = (float*)d_out;

    k_rough<<<NROWS, 128>>>(kpts, image_wh, Wr1, br1, Wr2, br2);
    k_repack<<<HID, 128>>>(Wc1, bc1, Wc2);
    k_match<<<NROWS, 128>>>(kpts, joint_vis, cam_R, cam_T, cam_f, cam_c,
                            image_wh, num_persons, bones);
    k_conv<<<NROWS, 256>>>(bc2, out);
}

// round 3
// speedup vs baseline: 1.6845x; 1.6845x over previous
#include <cuda_runtime.h>
#include <cuda_bf16.h>
#include <cstdint>
#include <math.h>

// Problem constants
#define NV 5
#define NB_ 32      // batch
#define NP 20
#define NJ 17
#define NBONES 16
#define ND 128
#define HR 1024
#define HID 1024
#define NROWS (NB_*NP)          // 640
#define NC (NJ + NBONES)        // 33
#define WROW 104                // padded weight row (99 Wc1 + bc1 + 3 Wc2 + pad)
#define KP 104                  // padded GEMM K (13 steps of 8)

// Scratch (device globals; no runtime allocation)
__device__ float g_rough[NROWS * NJ];
__device__ float g_xin[NROWS * NC * ND];          // (n, c, t)
__device__ float g_Wp[HID * WROW];

// ---------------------------------------------------------------------------
// helpers
// ---------------------------------------------------------------------------
__device__ __forceinline__ uint32_t f2tf32(float x) {
    uint32_t r; asm("cvt.rna.tf32.f32 %0, %1;" : "=r"(r) : "f"(x)); return r;
}

__device__ __forceinline__ void mma_tf32(float& c0, float& c1, float& c2, float& c3,
                                         uint32_t a0, uint32_t a1, uint32_t a2, uint32_t a3,
                                         uint32_t b0, uint32_t b1) {
    asm volatile("mma.sync.aligned.m16n8k8.row.col.f32.tf32.tf32.f32 "
                 "{%0,%1,%2,%3},{%4,%5,%6,%7},{%8,%9},{%0,%1,%2,%3};"
                 : "+f"(c0), "+f"(c1), "+f"(c2), "+f"(c3)
                 : "r"(a0), "r"(a1), "r"(a2), "r"(a3), "r"(b0), "r"(b1));
}

// ---------------------------------------------------------------------------
// Kernel A: rough depth MLP.  One block per (b,p).
// ---------------------------------------------------------------------------
__global__ __launch_bounds__(128) void k_rough(
    const float* __restrict__ kpts, const float* __restrict__ image_wh,
    const float* __restrict__ Wr1, const float* __restrict__ br1,
    const float* __restrict__ Wr2, const float* __restrict__ br2)
{
    __shared__ float xs[NJ * 2];
    __shared__ float hs[HR];
    const int n = blockIdx.x;
    const int b = n / NP, p = n % NP;
    const int tid = threadIdx.x;

    if (tid < NJ * 2) {
        int c = tid & 1;
        float wh = image_wh[c];  // view 0, batch 0
        xs[tid] = kpts[(((0 * NB_ + b) * NP + p) * NJ) * 2 + tid] / wh;
    }
    __syncthreads();

    for (int i = tid; i < HR; i += 128) {
        const float* wr = Wr1 + i * (NJ * 2);
        float acc = br1[i];
        #pragma unroll
        for (int m = 0; m < NJ * 2; ++m) acc += wr[m] * xs[m];
        hs[i] = fmaxf(acc, 0.0f);
    }
    __syncthreads();

    const int warp = tid >> 5, lane = tid & 31;
    for (int j = warp; j < NJ; j += 4) {
        const float* wr = Wr2 + j * HR;
        float acc = 0.0f;
        for (int i = lane; i < HR; i += 32) acc += hs[i] * wr[i];
        #pragma unroll
        for (int off = 16; off > 0; off >>= 1)
            acc += __shfl_down_sync(0xffffffffu, acc, off);
        if (lane == 0) g_rough[n * NJ + j] = (acc + br2[j]) * 1000.0f;
    }
}

// ---------------------------------------------------------------------------
// Kernel W: repack conv weights into 16B-aligned 104-float rows.
// row h: [0..98]=Wc1[h], [99]=bc1[h], [100..102]=Wc2[0][h][:], [103]=0
// (cols 99..103 are never touched by the GEMM because X rows 99..103 are 0)
// ---------------------------------------------------------------------------
__global__ void k_repack(const float* __restrict__ Wc1,
                         const float* __restrict__ bc1,
                         const float* __restrict__ Wc2)
{
    const int h = blockIdx.x;
    const int t = threadIdx.x;
    if (t >= WROW) return;
    float v;
    if (t < 99)        v = Wc1[h * 99 + t];
    else if (t == 99)  v = bc1[h];
    else if (t < 103)  v = Wc2[h * 3 + (t - 100)];
    else               v = 0.0f;
    g_Wp[h * WROW + t] = v;
}

// ---------------------------------------------------------------------------
// Kernel B: projection + person matching + scores for all 4 ref views.
// One block per (b,p); thread = depth bin d.
// ---------------------------------------------------------------------------
__global__ __launch_bounds__(128) void k_match(
    const float* __restrict__ kpts, const float* __restrict__ joint_vis,
    const float* __restrict__ cam_R, const float* __restrict__ cam_T,
    const float* __restrict__ cam_f, const float* __restrict__ cam_c,
    const float* __restrict__ image_wh, const int* __restrict__ num_persons,
    const int* __restrict__ bones)
{
    __shared__ float s_pr[NP * NJ * 2];
    __shared__ float s_vr[NP * NJ];
    __shared__ float s_rough[NJ];
    __shared__ float s_uvn[NJ * 2];
    __shared__ float s_R0[9], s_T0[3];
    __shared__ float s_Rr[9], s_Tr[3], s_fr[2], s_cr[2], s_wh[2];
    __shared__ int   s_bones[NBONES * 2];
    __shared__ float s_p2t[128 * 35];   // per-thread row of 17 (x,y) pairs, padded

    const int n = blockIdx.x;
    const int b = n / NP, p = n % NP;
    const int d = threadIdx.x;

    if (d < NJ) s_rough[d] = g_rough[n * NJ + d];
    if (d < 9)  s_R0[d] = cam_R[(0 * NB_ + b) * 9 + d];
    if (d < 3)  s_T0[d] = cam_T[(0 * NB_ + b) * 3 + d];
    if (d >= 32 && d < 32 + NBONES * 2) s_bones[d - 32] = bones[d - 32];
    if (d >= 64 && d < 64 + NJ * 2) {
        int m = d - 64;
        int c = m & 1;
        float cc = cam_c[(0 * NB_ + b) * 2 + c];
        float ff = cam_f[(0 * NB_ + b) * 2 + c];
        s_uvn[m] = (kpts[(((0 * NB_ + b) * NP + p) * NJ) * 2 + m] - cc) / ff;
    }

    float sc[NJ], bd[NJ], sc2[NBONES], bd2[NBONES];
    #pragma unroll
    for (int j = 0; j < NJ; ++j) { sc[j] = 0.0f; bd[j] = 0.0f; }
    #pragma unroll
    for (int e = 0; e < NBONES; ++e) { sc2[e] = 0.0f; bd2[e] = 0.0f; }

    const float label = ((float)d / 127.0f) * 6000.0f + 2000.0f;

    for (int rv = 1; rv < NV; ++rv) {
        __syncthreads();   // protect shared reuse across view iterations
        const int cambase = rv * NB_ + b;
        {
            const float* src = kpts + (size_t)cambase * NP * NJ * 2;
            for (int idx = d; idx < NP * NJ * 2; idx += 128) s_pr[idx] = src[idx];
            const float* vsrc = joint_vis + (size_t)cambase * NP * NJ;
            for (int idx = d; idx < NP * NJ; idx += 128) s_vr[idx] = vsrc[idx];
            if (d < 9) s_Rr[d] = cam_R[cambase * 9 + d];
            if (d < 3) s_Tr[d] = cam_T[cambase * 3 + d];
            if (d < 2) {
                s_fr[d] = cam_f[cambase * 2 + d];
                s_cr[d] = cam_c[cambase * 2 + d];
                s_wh[d] = image_wh[cambase * 2 + d];
            }
        }
        __syncthreads();
        const int np_r = num_persons[rv * NB_ + b];

        float px[NJ], py[NJ];
        #pragma unroll
        for (int j = 0; j < NJ; ++j) {
            float z  = label + s_rough[j];
            float cx = s_uvn[2 * j] * z;
            float cy = s_uvn[2 * j + 1] * z;
            float p0 = s_R0[0] * cx + s_R0[3] * cy + s_R0[6] * z + s_T0[0];
            float p1 = s_R0[1] * cx + s_R0[4] * cy + s_R0[7] * z + s_T0[1];
            float p2 = s_R0[2] * cx + s_R0[5] * cy + s_R0[8] * z + s_T0[2];
            float q0 = p0 - s_Tr[0], q1 = p1 - s_Tr[1], q2 = p2 - s_Tr[2];
            float xc0 = s_Rr[0] * q0 + s_Rr[1] * q1 + s_Rr[2] * q2;
            float xc1 = s_Rr[3] * q0 + s_Rr[4] * q1 + s_Rr[5] * q2;
            float xc2 = s_Rr[6] * q0 + s_Rr[7] * q1 + s_Rr[8] * q2;
            float inv = 1.0f / (xc2 + 1e-8f);
            px[j] = xc0 * inv * s_fr[0] + s_cr[0];
            py[j] = xc1 * inv * s_fr[1] + s_cr[1];
            s_p2t[d * 35 + 2 * j]     = px[j];
            s_p2t[d * 35 + 2 * j + 1] = py[j];
        }

        // argmin over candidate persons (first-min semantics)
        float best = 3.4e38f; int mm = 0;
        for (int q = 0; q < NP; ++q) {
            float num = 0.0f, den = 0.0f;
            #pragma unroll
            for (int j = 0; j < NJ; ++j) {
                float w  = s_vr[q * NJ + j];
                float dx = px[j] - s_pr[(q * NJ + j) * 2];
                float dy = py[j] - s_pr[(q * NJ + j) * 2 + 1];
                num += w * (dx * dx + dy * dy);
                den += w;
            }
            float val = num / (den + 1e-8f);
            if (q >= np_r) val = 100000.0f;
            if (val < best) { best = val; mm = q; }
        }

        const int mbase = mm * NJ;
        #pragma unroll
        for (int j = 0; j < NJ; ++j) {
            float mx = s_pr[(mbase + j) * 2];
            float my = s_pr[(mbase + j) * 2 + 1];
            float mv = s_vr[mbase + j];
            float dx = px[j] - mx, dy = py[j] - my;
            float score = expf(-sqrtf(dx * dx + dy * dy + 1e-12f) * (1.0f / 100.0f));
            float inb = (px[j] >= 0.0f && py[j] >= 0.0f &&
                         px[j] <= s_wh[0] - 1.0f && py[j] <= s_wh[1] - 1.0f) ? 1.0f : 0.0f;
            float bnd = inb * mv;
            sc[j] += score * bnd;
            bd[j] += bnd;
        }

        const float b20 = s_vr[mbase + 0];
        #pragma unroll
        for (int e = 0; e < NBONES; ++e) {
            int a = s_bones[2 * e], bb = s_bones[2 * e + 1];
            float pax = s_p2t[d * 35 + 2 * a], pay = s_p2t[d * 35 + 2 * a + 1];
            float pbx = s_p2t[d * 35 + 2 * bb], pby = s_p2t[d * 35 + 2 * bb + 1];
            float dxp = pax - pbx, dyp = pay - pby;
            float blp = sqrtf(dxp * dxp + dyp * dyp + 1e-12f);
            float max_ = s_pr[(mbase + a) * 2],  may_ = s_pr[(mbase + a) * 2 + 1];
            float mbx_ = s_pr[(mbase + bb) * 2], mby_ = s_pr[(mbase + bb) * 2 + 1];
            float dxm = max_ - mbx_, dym = may_ - mby_;
            float blm = sqrtf(dxm * dxm + dym * dym + 1e-12f);
            float sbl = expf(-fabsf(blm - blp) * 0.2f);
            sc2[e] += sbl * b20;
            bd2[e] += b20;
        }
    }

    float* xrow = g_xin + (size_t)n * NC * ND;
    #pragma unroll
    for (int j = 0; j < NJ; ++j)
        xrow[j * ND + d] = sc[j] / (bd[j] + 1e-8f);
    #pragma unroll
    for (int e = 0; e < NBONES; ++e)
        xrow[(NJ + e) * ND + d] = sc2[e] / (bd2[e] + 1e-8f);
}

// ---------------------------------------------------------------------------
// Kernel C (tensor-core): conv1 as tf32-split GEMM + fused conv2 + softmax +
// masked expectation.  One block (256 thr, 8 warps) per row n.
//
// GEMM:  Y[1024,128] = W[1024,KP] @ X[KP,128]   (X = im2col of xin, K pad 104)
// warp w owns h in [w*128, w*128+128): 8 m-tiles of 16, full N=128, 13 ksteps.
// 3-term tf32 split (hi*hi + hi*lo + lo*hi) ~ fp32 accuracy.
// After each m-tile: bias+relu -> per-warp shared strip -> 3-tap conv2
// accumulated into per-lane logit registers.
// ---------------------------------------------------------------------------
#define XHL_STRIDE 264     // (hi,lo) interleaved pairs, 132-pair row stride
#define Y_STRIDE   136
#define SMEM_DYN   ((KP*XHL_STRIDE + 8*16*Y_STRIDE + 8*128) * 4)

__global__ __launch_bounds__(256) void k_conv_tc(
    const float* __restrict__ bc2, float* __restrict__ out)
{
    extern __shared__ __align__(16) float smem[];
    float* sXhl = smem;                            // [KP][XHL_STRIDE]
    float* sY   = sXhl + KP * XHL_STRIDE;          // [8][16][Y_STRIDE]
    float* sLog = sY + 8 * 16 * Y_STRIDE;          // [8][128]
    __shared__ float s_logit[ND];
    __shared__ float s_red[ND];

    const int n   = blockIdx.x;
    const int tid = threadIdx.x;
    const int w    = tid >> 5;
    const int lane = tid & 31;
    const int g = lane >> 2, q = lane & 3;

    // ---- build im2col X in shared, pre-split hi/lo tf32 ----
    {
        const float* src = g_xin + (size_t)n * NC * ND;
        for (int idx = tid; idx < KP * ND; idx += 256) {
            int k = idx >> 7, t = idx & 127;
            float v = 0.0f;
            if (k < 99) {
                int c = k / 3, tap = k - 3 * c;
                int tt = t + tap - 1;
                if (tt >= 0 && tt < ND) v = src[c * ND + tt];
            }
            uint32_t hi = f2tf32(v);
            float lo = v - __uint_as_float(hi);
            sXhl[k * XHL_STRIDE + 2 * t]     = __uint_as_float(hi);
            sXhl[k * XHL_STRIDE + 2 * t + 1] = __uint_as_float(f2tf32(lo));
        }
        if (tid < ND) s_logit[tid] = bc2[0];
    }
    // zero Y halo columns (never overwritten afterwards)
    float* myY = sY + w * 16 * Y_STRIDE;
    if (lane < 16) { myY[lane * Y_STRIDE] = 0.0f; myY[lane * Y_STRIDE + 129] = 0.0f; }
    __syncthreads();

    float rL0 = 0.0f, rL1 = 0.0f, rL2 = 0.0f, rL3 = 0.0f;

    #pragma unroll 1
    for (int mt = 0; mt < 8; ++mt) {
        const int h0 = w * 128 + mt * 16;

        float acc[16][4];
        #pragma unroll
        for (int nt = 0; nt < 16; ++nt)
            #pragma unroll
            for (int j = 0; j < 4; ++j) acc[nt][j] = 0.0f;

        #pragma unroll
        for (int ks = 0; ks < 13; ++ks) {
            // A fragments from global (L2-resident), split hi/lo
            const float* wr = g_Wp + (size_t)(h0 + g) * WROW + ks * 8 + q;
            float a0f = wr[0];
            float a1f = wr[8 * WROW];
            float a2f = wr[4];
            float a3f = wr[8 * WROW + 4];
            uint32_t ah0 = f2tf32(a0f), ah1 = f2tf32(a1f), ah2 = f2tf32(a2f), ah3 = f2tf32(a3f);
            uint32_t al0 = f2tf32(a0f - __uint_as_float(ah0));
            uint32_t al1 = f2tf32(a1f - __uint_as_float(ah1));
            uint32_t al2 = f2tf32(a2f - __uint_as_float(ah2));
            uint32_t al3 = f2tf32(a3f - __uint_as_float(ah3));

            const float* xb0 = sXhl + (ks * 8 + q) * XHL_STRIDE;
            const float* xb4 = xb0 + 4 * XHL_STRIDE;
            #pragma unroll
            for (int nt = 0; nt < 16; ++nt) {
                int t = nt * 8 + g;
                float2 b0p = *(const float2*)&xb0[2 * t];
                float2 b1p = *(const float2*)&xb4[2 * t];
                uint32_t bh0 = __float_as_uint(b0p.x), bl0 = __float_as_uint(b0p.y);
                uint32_t bh1 = __float_as_uint(b1p.x), bl1 = __float_as_uint(b1p.y);
                mma_tf32(acc[nt][0], acc[nt][1], acc[nt][2], acc[nt][3],
                         ah0, ah1, ah2, ah3, bh0, bh1);
                mma_tf32(acc[nt][0], acc[nt][1], acc[nt][2], acc[nt][3],
                         ah0, ah1, ah2, ah3, bl0, bl1);
                mma_tf32(acc[nt][0], acc[nt][1], acc[nt][2], acc[nt][3],
                         al0, al1, al2, al3, bh0, bh1);
            }
        }

        // bias + relu -> per-warp Y strip
        const float bias_lo = g_Wp[(size_t)(h0 + g) * WROW + 99];
        const float bias_hi = g_Wp[(size_t)(h0 + g + 8) * WROW + 99];
        #pragma unroll
        for (int nt = 0; nt < 16; ++nt) {
            int t = nt * 8 + 2 * q;
            myY[g * Y_STRIDE + 1 + t]           = fmaxf(acc[nt][0] + bias_lo, 0.0f);
            myY[g * Y_STRIDE + 1 + t + 1]       = fmaxf(acc[nt][1] + bias_lo, 0.0f);
            myY[(g + 8) * Y_STRIDE + 1 + t]     = fmaxf(acc[nt][2] + bias_hi, 0.0f);
            myY[(g + 8) * Y_STRIDE + 1 + t + 1] = fmaxf(acc[nt][3] + bias_hi, 0.0f);
        }
        __syncwarp();

        // conv2: lane owns t in [4*lane, 4*lane+4)
        #pragma unroll
        for (int r = 0; r < 16; ++r) {
            const int h = h0 + r;
            const float* wc = g_Wp + (size_t)h * WROW + 100;
            float w0 = wc[0], w1 = wc[1], w2 = wc[2];
            const float* yr = myY + r * Y_STRIDE + 4 * lane;
            float y0 = yr[0], y1 = yr[1], y2 = yr[2], y3 = yr[3], y4 = yr[4], y5 = yr[5];
            rL0 += w0 * y0 + w1 * y1 + w2 * y2;
            rL1 += w0 * y1 + w1 * y2 + w2 * y3;
            rL2 += w0 * y2 + w1 * y3 + w2 * y4;
            rL3 += w0 * y3 + w1 * y4 + w2 * y5;
        }
        __syncwarp();   // reads done before next m-tile overwrites strip
    }

    // cross-warp logit reduction
    sLog[w * 128 + 4 * lane + 0] = rL0;
    sLog[w * 128 + 4 * lane + 1] = rL1;
    sLog[w * 128 + 4 * lane + 2] = rL2;
    sLog[w * 128 + 4 * lane + 3] = rL3;
    __syncthreads();
    if (tid < ND) {
        float s = s_logit[tid];
        #pragma unroll
        for (int ww = 0; ww < 8; ++ww) s += sLog[ww * 128 + tid];
        s_logit[tid] = s;
    }
    __syncthreads();

    // ---- softmax + argmax window + masked expectation ----
    if (tid < ND) s_red[tid] = s_logit[tid];
    __syncthreads();
    for (int s = 64; s > 0; s >>= 1) {
        if (tid < s) s_red[tid] = fmaxf(s_red[tid], s_red[tid + s]);
        __syncthreads();
    }
    const float mx = s_red[0];
    __syncthreads();

    if (tid < ND) s_red[tid] = (s_logit[tid] == mx) ? (float)tid : 1.0e9f;
    __syncthreads();
    for (int s = 64; s > 0; s >>= 1) {
        if (tid < s) s_red[tid] = fminf(s_red[tid], s_red[tid + s]);
        __syncthreads();
    }
    const int idx = (int)s_red[0];
    __syncthreads();

    float e = 0.0f;
    if (tid < ND) e = expf(s_logit[tid] - mx);

    if (tid < ND) s_red[tid] = e;
    __syncthreads();
    for (int s = 64; s > 0; s >>= 1) {
        if (tid < s) s_red[tid] += s_red[tid + s];
        __syncthreads();
    }
    const float S = s_red[0];
    __syncthreads();

    const float me = (tid < ND && abs(tid - idx) <= 5) ? e : 0.0f;

    if (tid < ND) s_red[tid] = me;
    __syncthreads();
    for (int s = 64; s > 0; s >>= 1) {
        if (tid < s) s_red[tid] += s_red[tid + s];
        __syncthreads();
    }
    const float den = s_red[0];
    __syncthreads();

    if (tid < ND) s_red[tid] = me * (float)tid;
    __syncthreads();
    for (int s = 64; s > 0; s >>= 1) {
        if (tid < s) s_red[tid] += s_red[tid + s];
        __syncthreads();
    }
    if (tid == 0) {
        float pred = s_red[0] / (den + 1e-8f * S);
        out[n] = pred * (6000.0f / 127.0f) + 2000.0f;
    }
}

// ---------------------------------------------------------------------------
extern "C" void kernel_launch(void* const* d_in, const int* in_sizes, int n_in,
                              void* d_out, int out_size)
{
    const float* kpts        = (const float*)d_in[0];
    const float* joint_vis   = (const float*)d_in[2];
    const float* cam_R       = (const float*)d_in[5];
    const float* cam_T       = (const float*)d_in[6];
    const float* cam_f       = (const float*)d_in[7];
    const float* cam_c       = (const float*)d_in[8];
    const float* image_wh    = (const float*)d_in[9];
    const int*   num_persons = (const int*)d_in[10];
    const float* Wr1         = (const float*)d_in[11];
    const float* br1         = (const float*)d_in[12];
    const float* Wr2         = (const float*)d_in[13];
    const float* br2         = (const float*)d_in[14];
    const float* Wc1         = (const float*)d_in[15];
    const float* bc1         = (const float*)d_in[16];
    const float* Wc2         = (const float*)d_in[17];
    const float* bc2         = (const float*)d_in[18];
    const int*   bones       = (const int*)d_in[19];
    float* out = (float*)d_out;

    static bool attr_done = false;
    if (!attr_done) {
        cudaFuncSetAttribute(k_conv_tc, cudaFuncAttributeMaxDynamicSharedMemorySize,
                             SMEM_DYN);
        attr_done = true;
    }

    k_rough<<<NROWS, 128>>>(kpts, image_wh, Wr1, br1, Wr2, br2);
    k_repack<<<HID, 128>>>(Wc1, bc1, Wc2);
    k_match<<<NROWS, 128>>>(kpts, joint_vis, cam_R, cam_T, cam_f, cam_c,
                            image_wh, num_persons, bones);
    k_conv_tc<<<NROWS, 256, SMEM_DYN>>>(bc2, out);
}

// round 4
// speedup vs baseline: 2.3406x; 1.3895x over previous
#include <cuda_runtime.h>
#include <cuda_bf16.h>
#include <cstdint>
#include <math.h>

// Problem constants
#define NV 5
#define NB_ 32      // batch
#define NP 20
#define NJ 17
#define NBONES 16
#define ND 128
#define HR 1024
#define HID 1024
#define NROWS (NB_*NP)          // 640
#define NC (NJ + NBONES)        // 33
#define KP16 112                // padded GEMM K (7 steps of 16)
#define NKS 7
#define NKP 56                  // k-pairs
#define XS 136                  // shared X row stride (words) -> banks 8q+g distinct
#define YS 136                  // Y strip row stride

// Scratch (device globals; no runtime allocation)
__device__ float g_rough[NROWS * NJ];
__device__ float g_xin[NROWS * NC * ND];            // (n, c, t)
__device__ uint4 g_Wa_hi[64 * NKS * 32];            // A fragments, hi split
__device__ uint4 g_Wa_lo[64 * NKS * 32];            // A fragments, lo split

// ---------------------------------------------------------------------------
// helpers
// ---------------------------------------------------------------------------
__device__ __forceinline__ uint32_t pack_bf16x2(float v0, float v1) {
    // low half = v0 (even k), high half = v1 (odd k)
    __nv_bfloat16 b0 = __float2bfloat16(v0);
    __nv_bfloat16 b1 = __float2bfloat16(v1);
    return ((uint32_t)__bfloat16_as_ushort(b1) << 16) | (uint32_t)__bfloat16_as_ushort(b0);
}

__device__ __forceinline__ void split_pack(float v0, float v1, uint32_t& hi, uint32_t& lo) {
    __nv_bfloat16 h0 = __float2bfloat16(v0);
    __nv_bfloat16 h1 = __float2bfloat16(v1);
    float r0 = v0 - __bfloat162float(h0);
    float r1 = v1 - __bfloat162float(h1);
    hi = ((uint32_t)__bfloat16_as_ushort(h1) << 16) | (uint32_t)__bfloat16_as_ushort(h0);
    lo = pack_bf16x2(r0, r1);
}

__device__ __forceinline__ void mma_bf16(float* c,
                                         uint32_t a0, uint32_t a1, uint32_t a2, uint32_t a3,
                                         uint32_t b0, uint32_t b1) {
    asm volatile("mma.sync.aligned.m16n8k16.row.col.f32.bf16.bf16.f32 "
                 "{%0,%1,%2,%3},{%4,%5,%6,%7},{%8,%9},{%0,%1,%2,%3};"
                 : "+f"(c[0]), "+f"(c[1]), "+f"(c[2]), "+f"(c[3])
                 : "r"(a0), "r"(a1), "r"(a2), "r"(a3), "r"(b0), "r"(b1));
}

// ---------------------------------------------------------------------------
// Kernel A: rough depth MLP.  One block per (b,p).
// ---------------------------------------------------------------------------
__global__ __launch_bounds__(128) void k_rough(
    const float* __restrict__ kpts, const float* __restrict__ image_wh,
    const float* __restrict__ Wr1, const float* __restrict__ br1,
    const float* __restrict__ Wr2, const float* __restrict__ br2)
{
    __shared__ float xs[NJ * 2];
    __shared__ float hs[HR];
    const int n = blockIdx.x;
    const int b = n / NP, p = n % NP;
    const int tid = threadIdx.x;

    if (tid < NJ * 2) {
        int c = tid & 1;
        float wh = image_wh[c];  // view 0, batch 0
        xs[tid] = kpts[(((0 * NB_ + b) * NP + p) * NJ) * 2 + tid] / wh;
    }
    __syncthreads();

    for (int i = tid; i < HR; i += 128) {
        const float* wr = Wr1 + i * (NJ * 2);
        float acc = br1[i];
        #pragma unroll
        for (int m = 0; m < NJ * 2; ++m) acc += wr[m] * xs[m];
        hs[i] = fmaxf(acc, 0.0f);
    }
    __syncthreads();

    const int warp = tid >> 5, lane = tid & 31;
    for (int j = warp; j < NJ; j += 4) {
        const float* wr = Wr2 + j * HR;
        float acc = 0.0f;
        for (int i = lane; i < HR; i += 32) acc += hs[i] * wr[i];
        #pragma unroll
        for (int off = 16; off > 0; off >>= 1)
            acc += __shfl_down_sync(0xffffffffu, acc, off);
        if (lane == 0) g_rough[n * NJ + j] = (acc + br2[j]) * 1000.0f;
    }
}

// ---------------------------------------------------------------------------
// Kernel W: pack conv1 weights into bf16 hi/lo mma A-fragments.
// tile = blockIdx.x (h-tile of 16), ks = blockIdx.y (k-chunk of 16).
// Fragment layout (m16n8k16): a0={A[g][2q],A[g][2q+1]}, a1={A[g+8][..]},
// a2={A[g][2q+8],..+9}, a3={A[g+8][2q+8],..}.
// ---------------------------------------------------------------------------
__global__ void k_repack_frag(const float* __restrict__ Wc1)
{
    const int tile = blockIdx.x;      // 0..63
    const int ks   = blockIdx.y;      // 0..6
    const int lane = threadIdx.x;     // 0..31
    const int g = lane >> 2, q = lane & 3;
    const int hA = tile * 16 + g, hB = hA + 8;
    const int k0 = ks * 16;

    float v[8];
    int hh[4] = {hA, hB, hA, hB};
    int kk[4] = {k0 + 2*q, k0 + 2*q, k0 + 2*q + 8, k0 + 2*q + 8};
    #pragma unroll
    for (int r = 0; r < 4; ++r) {
        int h = hh[r], k = kk[r];
        v[2*r]     = (k     < 99) ? Wc1[h * 99 + k]     : 0.0f;
        v[2*r + 1] = (k + 1 < 99) ? Wc1[h * 99 + k + 1] : 0.0f;
    }
    uint32_t hi[4], lo[4];
    #pragma unroll
    for (int r = 0; r < 4; ++r) split_pack(v[2*r], v[2*r+1], hi[r], lo[r]);

    const int o = (tile * NKS + ks) * 32 + lane;
    g_Wa_hi[o] = make_uint4(hi[0], hi[1], hi[2], hi[3]);
    g_Wa_lo[o] = make_uint4(lo[0], lo[1], lo[2], lo[3]);
}

// ---------------------------------------------------------------------------
// Kernel B: projection + person matching + scores for all 4 ref views.
// One block per (b,p); thread = depth bin d.
// ---------------------------------------------------------------------------
__global__ __launch_bounds__(128) void k_match(
    const float* __restrict__ kpts, const float* __restrict__ joint_vis,
    const float* __restrict__ cam_R, const float* __restrict__ cam_T,
    const float* __restrict__ cam_f, const float* __restrict__ cam_c,
    const float* __restrict__ image_wh, const int* __restrict__ num_persons,
    const int* __restrict__ bones)
{
    __shared__ float s_pr[NP * NJ * 2];
    __shared__ float s_vr[NP * NJ];
    __shared__ float s_rough[NJ];
    __shared__ float s_uvn[NJ * 2];
    __shared__ float s_R0[9], s_T0[3];
    __shared__ float s_Rr[9], s_Tr[3], s_fr[2], s_cr[2], s_wh[2];
    __shared__ int   s_bones[NBONES * 2];
    __shared__ float s_p2t[128 * 35];

    const int n = blockIdx.x;
    const int b = n / NP, p = n % NP;
    const int d = threadIdx.x;

    if (d < NJ) s_rough[d] = g_rough[n * NJ + d];
    if (d < 9)  s_R0[d] = cam_R[(0 * NB_ + b) * 9 + d];
    if (d < 3)  s_T0[d] = cam_T[(0 * NB_ + b) * 3 + d];
    if (d >= 32 && d < 32 + NBONES * 2) s_bones[d - 32] = bones[d - 32];
    if (d >= 64 && d < 64 + NJ * 2) {
        int m = d - 64;
        int c = m & 1;
        float cc = cam_c[(0 * NB_ + b) * 2 + c];
        float ff = cam_f[(0 * NB_ + b) * 2 + c];
        s_uvn[m] = (kpts[(((0 * NB_ + b) * NP + p) * NJ) * 2 + m] - cc) / ff;
    }

    float sc[NJ], bd[NJ], sc2[NBONES], bd2[NBONES];
    #pragma unroll
    for (int j = 0; j < NJ; ++j) { sc[j] = 0.0f; bd[j] = 0.0f; }
    #pragma unroll
    for (int e = 0; e < NBONES; ++e) { sc2[e] = 0.0f; bd2[e] = 0.0f; }

    const float label = ((float)d / 127.0f) * 6000.0f + 2000.0f;

    for (int rv = 1; rv < NV; ++rv) {
        __syncthreads();
        const int cambase = rv * NB_ + b;
        {
            const float* src = kpts + (size_t)cambase * NP * NJ * 2;
            for (int idx = d; idx < NP * NJ * 2; idx += 128) s_pr[idx] = src[idx];
            const float* vsrc = joint_vis + (size_t)cambase * NP * NJ;
            for (int idx = d; idx < NP * NJ; idx += 128) s_vr[idx] = vsrc[idx];
            if (d < 9) s_Rr[d] = cam_R[cambase * 9 + d];
            if (d < 3) s_Tr[d] = cam_T[cambase * 3 + d];
            if (d < 2) {
                s_fr[d] = cam_f[cambase * 2 + d];
                s_cr[d] = cam_c[cambase * 2 + d];
                s_wh[d] = image_wh[cambase * 2 + d];
            }
        }
        __syncthreads();
        const int np_r = num_persons[rv * NB_ + b];

        float px[NJ], py[NJ];
        #pragma unroll
        for (int j = 0; j < NJ; ++j) {
            float z  = label + s_rough[j];
            float cx = s_uvn[2 * j] * z;
            float cy = s_uvn[2 * j + 1] * z;
            float p0 = s_R0[0] * cx + s_R0[3] * cy + s_R0[6] * z + s_T0[0];
            float p1 = s_R0[1] * cx + s_R0[4] * cy + s_R0[7] * z + s_T0[1];
            float p2 = s_R0[2] * cx + s_R0[5] * cy + s_R0[8] * z + s_T0[2];
            float q0 = p0 - s_Tr[0], q1 = p1 - s_Tr[1], q2 = p2 - s_Tr[2];
            float xc0 = s_Rr[0] * q0 + s_Rr[1] * q1 + s_Rr[2] * q2;
            float xc1 = s_Rr[3] * q0 + s_Rr[4] * q1 + s_Rr[5] * q2;
            float xc2 = s_Rr[6] * q0 + s_Rr[7] * q1 + s_Rr[8] * q2;
            float inv = 1.0f / (xc2 + 1e-8f);
            px[j] = xc0 * inv * s_fr[0] + s_cr[0];
            py[j] = xc1 * inv * s_fr[1] + s_cr[1];
            s_p2t[d * 35 + 2 * j]     = px[j];
            s_p2t[d * 35 + 2 * j + 1] = py[j];
        }

        float best = 3.4e38f; int mm = 0;
        for (int q = 0; q < NP; ++q) {
            float num = 0.0f, den = 0.0f;
            #pragma unroll
            for (int j = 0; j < NJ; ++j) {
                float w  = s_vr[q * NJ + j];
                float dx = px[j] - s_pr[(q * NJ + j) * 2];
                float dy = py[j] - s_pr[(q * NJ + j) * 2 + 1];
                num += w * (dx * dx + dy * dy);
                den += w;
            }
            float val = num / (den + 1e-8f);
            if (q >= np_r) val = 100000.0f;
            if (val < best) { best = val; mm = q; }
        }

        const int mbase = mm * NJ;
        #pragma unroll
        for (int j = 0; j < NJ; ++j) {
            float mx = s_pr[(mbase + j) * 2];
            float my = s_pr[(mbase + j) * 2 + 1];
            float mv = s_vr[mbase + j];
            float dx = px[j] - mx, dy = py[j] - my;
            float score = expf(-sqrtf(dx * dx + dy * dy + 1e-12f) * (1.0f / 100.0f));
            float inb = (px[j] >= 0.0f && py[j] >= 0.0f &&
                         px[j] <= s_wh[0] - 1.0f && py[j] <= s_wh[1] - 1.0f) ? 1.0f : 0.0f;
            float bnd = inb * mv;
            sc[j] += score * bnd;
            bd[j] += bnd;
        }

        const float b20 = s_vr[mbase + 0];
        #pragma unroll
        for (int e = 0; e < NBONES; ++e) {
            int a = s_bones[2 * e], bb = s_bones[2 * e + 1];
            float pax = s_p2t[d * 35 + 2 * a], pay = s_p2t[d * 35 + 2 * a + 1];
            float pbx = s_p2t[d * 35 + 2 * bb], pby = s_p2t[d * 35 + 2 * bb + 1];
            float dxp = pax - pbx, dyp = pay - pby;
            float blp = sqrtf(dxp * dxp + dyp * dyp + 1e-12f);
            float max_ = s_pr[(mbase + a) * 2],  may_ = s_pr[(mbase + a) * 2 + 1];
            float mbx_ = s_pr[(mbase + bb) * 2], mby_ = s_pr[(mbase + bb) * 2 + 1];
            float dxm = max_ - mbx_, dym = may_ - mby_;
            float blm = sqrtf(dxm * dxm + dym * dym + 1e-12f);
            float sbl = expf(-fabsf(blm - blp) * 0.2f);
            sc2[e] += sbl * b20;
            bd2[e] += b20;
        }
    }

    float* xrow = g_xin + (size_t)n * NC * ND;
    #pragma unroll
    for (int j = 0; j < NJ; ++j)
        xrow[j * ND + d] = sc[j] / (bd[j] + 1e-8f);
    #pragma unroll
    for (int e = 0; e < NBONES; ++e)
        xrow[(NJ + e) * ND + d] = sc2[e] / (bd2[e] + 1e-8f);
}

// ---------------------------------------------------------------------------
// Kernel C: conv1 as bf16-split m16n8k16 GEMM + fused conv2 + softmax +
// masked expectation.  One block (256 thr, 8 warps) per row n.
// Warp w owns h in [w*128, (w+1)*128): 4 mt-iterations of M=32 (2 m16 tiles
// sharing B fragments).  3-term bf16 split: AhBh + AhBl + AlBh.
// ---------------------------------------------------------------------------
#define SMEM_DYN ((NKP*XS*2 + 8*16*YS + 8*128) * 4)

__global__ __launch_bounds__(256) void k_conv_tc(
    const float* __restrict__ bc1, const float* __restrict__ Wc2,
    const float* __restrict__ bc2, float* __restrict__ out)
{
    extern __shared__ __align__(16) uint32_t smem_u[];
    uint32_t* sXhi = smem_u;                      // [NKP][XS]
    uint32_t* sXlo = sXhi + NKP * XS;             // [NKP][XS]
    float* sY   = (float*)(sXlo + NKP * XS);      // [8][16][YS]
    float* sLog = sY + 8 * 16 * YS;               // [8][128]
    __shared__ float s_logit[ND];
    __shared__ float s_red[ND];

    const int n   = blockIdx.x;
    const int tid = threadIdx.x;
    const int w    = tid >> 5;
    const int lane = tid & 31;
    const int g = lane >> 2, q = lane & 3;

    // ---- build im2col X in shared, bf16 hi/lo split, k-pairs packed ----
    {
        const float* src = g_xin + (size_t)n * NC * ND;
        for (int idx = tid; idx < NKP * ND; idx += 256) {
            int kp = idx >> 7, t = idx & 127;
            float v0 = 0.0f, v1 = 0.0f;
            int k0 = 2 * kp;
            if (k0 < 99) {
                int c = k0 / 3, tap = k0 - 3 * c;
                int tt = t + tap - 1;
                if (tt >= 0 && tt < ND) v0 = src[c * ND + tt];
            }
            int k1 = k0 + 1;
            if (k1 < 99) {
                int c = k1 / 3, tap = k1 - 3 * c;
                int tt = t + tap - 1;
                if (tt >= 0 && tt < ND) v1 = src[c * ND + tt];
            }
            uint32_t hi, lo;
            split_pack(v0, v1, hi, lo);
            sXhi[kp * XS + t] = hi;
            sXlo[kp * XS + t] = lo;
        }
        if (tid < ND) s_logit[tid] = bc2[0];
    }
    // zero Y halo columns
    float* myY = sY + w * 16 * YS;
    if (lane < 16) { myY[lane * YS] = 0.0f; myY[lane * YS + 129] = 0.0f; }
    __syncthreads();

    float rL[4] = {0.0f, 0.0f, 0.0f, 0.0f};

    #pragma unroll 1
    for (int mt = 0; mt < 4; ++mt) {
        const int h0 = w * 128 + mt * 32;
        const int tile0 = h0 >> 4;

        float acc0[16][4], acc1[16][4];
        #pragma unroll
        for (int nt = 0; nt < 16; ++nt)
            #pragma unroll
            for (int j = 0; j < 4; ++j) { acc0[nt][j] = 0.0f; acc1[nt][j] = 0.0f; }

        #pragma unroll
        for (int ks = 0; ks < NKS; ++ks) {
            const uint4 ah0 = g_Wa_hi[(tile0 * NKS + ks) * 32 + lane];
            const uint4 al0 = g_Wa_lo[(tile0 * NKS + ks) * 32 + lane];
            const uint4 ah1 = g_Wa_hi[((tile0 + 1) * NKS + ks) * 32 + lane];
            const uint4 al1 = g_Wa_lo[((tile0 + 1) * NKS + ks) * 32 + lane];
            const int kp0 = ks * 8 + q;
            const uint32_t* xh0 = sXhi + kp0 * XS;
            const uint32_t* xh4 = xh0 + 4 * XS;
            const uint32_t* xl0 = sXlo + kp0 * XS;
            const uint32_t* xl4 = xl0 + 4 * XS;

            #pragma unroll
            for (int nt = 0; nt < 16; ++nt) {
                const int t = nt * 8 + g;
                uint32_t b0h = xh0[t], b1h = xh4[t];
                uint32_t b0l = xl0[t], b1l = xl4[t];
                mma_bf16(acc0[nt], ah0.x, ah0.y, ah0.z, ah0.w, b0h, b1h);
                mma_bf16(acc1[nt], ah1.x, ah1.y, ah1.z, ah1.w, b0h, b1h);
                mma_bf16(acc0[nt], ah0.x, ah0.y, ah0.z, ah0.w, b0l, b1l);
                mma_bf16(acc1[nt], ah1.x, ah1.y, ah1.z, ah1.w, b0l, b1l);
                mma_bf16(acc0[nt], al0.x, al0.y, al0.z, al0.w, b0h, b1h);
                mma_bf16(acc1[nt], al1.x, al1.y, al1.z, al1.w, b0h, b1h);
            }
        }

        // ---- epilogue: two 16-row tiles through the per-warp Y strip ----
        #pragma unroll
        for (int sub = 0; sub < 2; ++sub) {
            const int ht = h0 + sub * 16;
            const float bias0 = bc1[ht + g];
            const float bias1 = bc1[ht + g + 8];
            #pragma unroll
            for (int nt = 0; nt < 16; ++nt) {
                const int t = nt * 8 + 2 * q;
                const float* a = sub ? acc1[nt] : acc0[nt];
                myY[g * YS + 1 + t]           = fmaxf(a[0] + bias0, 0.0f);
                myY[g * YS + 2 + t]           = fmaxf(a[1] + bias0, 0.0f);
                myY[(g + 8) * YS + 1 + t]     = fmaxf(a[2] + bias1, 0.0f);
                myY[(g + 8) * YS + 2 + t]     = fmaxf(a[3] + bias1, 0.0f);
            }
            __syncwarp();

            // conv2: lane owns t = lane + 32m
            #pragma unroll
            for (int r = 0; r < 16; ++r) {
                const int h = ht + r;
                const float w0 = Wc2[h * 3], w1 = Wc2[h * 3 + 1], w2 = Wc2[h * 3 + 2];
                const float* base = myY + r * YS + lane;
                #pragma unroll
                for (int m = 0; m < 4; ++m) {
                    float yp = base[32 * m];       // y[t-1]
                    float yc = base[32 * m + 1];   // y[t]
                    float yn = base[32 * m + 2];   // y[t+1]
                    rL[m] += w0 * yp + w1 * yc + w2 * yn;
                }
            }
            __syncwarp();
        }
    }

    // cross-warp logit reduction
    #pragma unroll
    for (int m = 0; m < 4; ++m) sLog[w * 128 + lane + 32 * m] = rL[m];
    __syncthreads();
    if (tid < ND) {
        float s = s_logit[tid];
        #pragma unroll
        for (int ww = 0; ww < 8; ++ww) s += sLog[ww * 128 + tid];
        s_logit[tid] = s;
    }
    __syncthreads();

    // ---- softmax + argmax window + masked expectation ----
    if (tid < ND) s_red[tid] = s_logit[tid];
    __syncthreads();
    for (int s = 64; s > 0; s >>= 1) {
        if (tid < s) s_red[tid] = fmaxf(s_red[tid], s_red[tid + s]);
        __syncthreads();
    }
    const float mx = s_red[0];
    __syncthreads();

    if (tid < ND) s_red[tid] = (s_logit[tid] == mx) ? (float)tid : 1.0e9f;
    __syncthreads();
    for (int s = 64; s > 0; s >>= 1) {
        if (tid < s) s_red[tid] = fminf(s_red[tid], s_red[tid + s]);
        __syncthreads();
    }
    const int idx = (int)s_red[0];
    __syncthreads();

    float e = 0.0f;
    if (tid < ND) e = expf(s_logit[tid] - mx);

    if (tid < ND) s_red[tid] = e;
    __syncthreads();
    for (int s = 64; s > 0; s >>= 1) {
        if (tid < s) s_red[tid] += s_red[tid + s];
        __syncthreads();
    }
    const float S = s_red[0];
    __syncthreads();

    const float me = (tid < ND && abs(tid - idx) <= 5) ? e : 0.0f;

    if (tid < ND) s_red[tid] = me;
    __syncthreads();
    for (int s = 64; s > 0; s >>= 1) {
        if (tid < s) s_red[tid] += s_red[tid + s];
        __syncthreads();
    }
    const float den = s_red[0];
    __syncthreads();

    if (tid < ND) s_red[tid] = me * (float)tid;
    __syncthreads();
    for (int s = 64; s > 0; s >>= 1) {
        if (tid < s) s_red[tid] += s_red[tid + s];
        __syncthreads();
    }
    if (tid == 0) {
        float pred = s_red[0] / (den + 1e-8f * S);
        out[n] = pred * (6000.0f / 127.0f) + 2000.0f;
    }
}

// ---------------------------------------------------------------------------
extern "C" void kernel_launch(void* const* d_in, const int* in_sizes, int n_in,
                              void* d_out, int out_size)
{
    const float* kpts        = (const float*)d_in[0];
    const float* joint_vis   = (const float*)d_in[2];
    const float* cam_R       = (const float*)d_in[5];
    const float* cam_T       = (const float*)d_in[6];
    const float* cam_f       = (const float*)d_in[7];
    const float* cam_c       = (const float*)d_in[8];
    const float* image_wh    = (const float*)d_in[9];
    const int*   num_persons = (const int*)d_in[10];
    const float* Wr1         = (const float*)d_in[11];
    const float* br1         = (const float*)d_in[12];
    const float* Wr2         = (const float*)d_in[13];
    const float* br2         = (const float*)d_in[14];
    const float* Wc1         = (const float*)d_in[15];
    const float* bc1         = (const float*)d_in[16];
    const float* Wc2         = (const float*)d_in[17];
    const float* bc2         = (const float*)d_in[18];
    const int*   bones       = (const int*)d_in[19];
    float* out = (float*)d_out;

    static bool attr_done = false;
    if (!attr_done) {
        cudaFuncSetAttribute(k_conv_tc, cudaFuncAttributeMaxDynamicSharedMemorySize,
                             SMEM_DYN);
        attr_done = true;
    }

    k_rough<<<NROWS, 128>>>(kpts, image_wh, Wr1, br1, Wr2, br2);
    k_repack_frag<<<dim3(64, NKS), 32>>>(Wc1);
    k_match<<<NROWS, 128>>>(kpts, joint_vis, cam_R, cam_T, cam_f, cam_c,
                            image_wh, num_persons, bones);
    k_conv_tc<<<NROWS, 256, SMEM_DYN>>>(bc1, Wc2, bc2, out);
}

// round 8
// speedup vs baseline: 2.7632x; 1.1806x over previous
#include <cuda_runtime.h>
#include <cuda_bf16.h>
#include <cstdint>
#include <math.h>

// Problem constants
#define NV 5
#define NB_ 32      // batch
#define NP 20
#define NJ 17
#define NBONES 16
#define ND 128
#define HR 1024
#define HID 1024
#define NROWS (NB_*NP)          // 640
#define NC (NJ + NBONES)        // 33
#define NKS 7                   // k-steps of 16 (K=112)
#define NMT 32                  // m-steps of 32 h
#define XROW 240                // X row stride in bytes (56 kpairs = 224B + pad)
#define XBYTES (128 * XROW)     // 30720
#define AFRAG  (NKS * 4 * 32 * 16)          // 14336
#define ACHUNK (AFRAG + 32 * 16)            // + meta {bc1,w0,w1,w2} = 14848
#define SMEM_DYN (2 * XBYTES + 2 * ACHUNK)  // 91136

// Scratch (device globals; no runtime allocation)
__device__ float g_rough[NROWS * NJ];
__device__ float g_xin[NROWS * NC * ND];                     // (n, c, t)
__device__ __align__(16) unsigned char g_Wst[NMT * ACHUNK];  // A frags + meta

// ---------------------------------------------------------------------------
// helpers
// ---------------------------------------------------------------------------
__device__ __forceinline__ void split_pack(float v0, float v1, uint32_t& hi, uint32_t& lo) {
    __nv_bfloat16 h0 = __float2bfloat16(v0);
    __nv_bfloat16 h1 = __float2bfloat16(v1);
    float r0 = v0 - __bfloat162float(h0);
    float r1 = v1 - __bfloat162float(h1);
    __nv_bfloat16 l0 = __float2bfloat16(r0);
    __nv_bfloat16 l1 = __float2bfloat16(r1);
    hi = ((uint32_t)__bfloat16_as_ushort(h1) << 16) | (uint32_t)__bfloat16_as_ushort(h0);
    lo = ((uint32_t)__bfloat16_as_ushort(l1) << 16) | (uint32_t)__bfloat16_as_ushort(l0);
}

__device__ __forceinline__ uint32_t smem_u32(const void* p) {
    uint32_t a;
    asm("{ .reg .u64 t; cvta.to.shared.u64 t, %1; cvt.u32.u64 %0, t; }" : "=r"(a) : "l"(p));
    return a;
}

__device__ __forceinline__ void mma_bf16(float* c,
                                         uint32_t a0, uint32_t a1, uint32_t a2, uint32_t a3,
                                         uint32_t b0, uint32_t b1) {
    asm volatile("mma.sync.aligned.m16n8k16.row.col.f32.bf16.bf16.f32 "
                 "{%0,%1,%2,%3},{%4,%5,%6,%7},{%8,%9},{%0,%1,%2,%3};"
                 : "+f"(c[0]), "+f"(c[1]), "+f"(c[2]), "+f"(c[3])
                 : "r"(a0), "r"(a1), "r"(a2), "r"(a3), "r"(b0), "r"(b1));
}

__device__ __forceinline__ void ldsm4(uint32_t* r, uint32_t addr) {
    asm volatile("ldmatrix.sync.aligned.m8n8.x4.shared.b16 {%0,%1,%2,%3}, [%4];"
                 : "=r"(r[0]), "=r"(r[1]), "=r"(r[2]), "=r"(r[3]) : "r"(addr));
}

__device__ __forceinline__ void cp16(uint32_t s, const void* g) {
    asm volatile("cp.async.cg.shared.global [%0], [%1], 16;" :: "r"(s), "l"(g));
}
__device__ __forceinline__ void cp_commit() { asm volatile("cp.async.commit_group;" ::: "memory"); }
__device__ __forceinline__ void cp_wait1()  { asm volatile("cp.async.wait_group 1;" ::: "memory"); }
__device__ __forceinline__ void cp_wait0()  { asm volatile("cp.async.wait_group 0;" ::: "memory"); }

__device__ __forceinline__ float fsqrt_ap(float x) {
    float r; asm("sqrt.approx.f32 %0, %1;" : "=f"(r) : "f"(x)); return r;
}

// ---------------------------------------------------------------------------
// Kernel A: rough depth MLP.  One block per (b,p).
// ---------------------------------------------------------------------------
__global__ __launch_bounds__(128) void k_rough(
    const float* __restrict__ kpts, const float* __restrict__ image_wh,
    const float* __restrict__ Wr1, const float* __restrict__ br1,
    const float* __restrict__ Wr2, const float* __restrict__ br2)
{
    __shared__ float xs[NJ * 2];
    __shared__ float hs[HR];
    const int n = blockIdx.x;
    const int b = n / NP, p = n % NP;
    const int tid = threadIdx.x;

    if (tid < NJ * 2) {
        int c = tid & 1;
        float wh = image_wh[c];
        xs[tid] = kpts[(((0 * NB_ + b) * NP + p) * NJ) * 2 + tid] / wh;
    }
    __syncthreads();

    for (int i = tid; i < HR; i += 128) {
        const float* wr = Wr1 + i * (NJ * 2);
        float acc = br1[i];
        #pragma unroll
        for (int m = 0; m < NJ * 2; ++m) acc += wr[m] * xs[m];
        hs[i] = fmaxf(acc, 0.0f);
    }
    __syncthreads();

    const int warp = tid >> 5, lane = tid & 31;
    for (int j = warp; j < NJ; j += 4) {
        const float* wr = Wr2 + j * HR;
        float acc = 0.0f;
        for (int i = lane; i < HR; i += 32) acc += hs[i] * wr[i];
        #pragma unroll
        for (int off = 16; off > 0; off >>= 1)
            acc += __shfl_down_sync(0xffffffffu, acc, off);
        if (lane == 0) g_rough[n * NJ + j] = (acc + br2[j]) * 1000.0f;
    }
}

// ---------------------------------------------------------------------------
// Kernel W: pack conv1 weights into per-mt A-fragment chunks + meta.
// chunk mt layout: [ks 7][part 4][lane 32] uint4  (part: 0=hi tile0, 1=hi
// tile1, 2=lo tile0, 3=lo tile1), then [hl 32] float4 {bc1, w0, w1, w2}.
// m16n8k16 A frag (row-major): a0=(g,2q..), a1=(g+8,2q..), a2=(g,2q+8..),
// a3=(g+8,2q+8..).
// ---------------------------------------------------------------------------
__global__ __launch_bounds__(256) void k_repack_frag(
    const float* __restrict__ Wc1, const float* __restrict__ bc1,
    const float* __restrict__ Wc2)
{
    const int mt  = blockIdx.x;
    const int tid = threadIdx.x;
    unsigned char* chunk = g_Wst + (size_t)mt * ACHUNK;

    if (tid < 224) {
        const int ks = tid >> 5, lane = tid & 31;
        const int g = lane >> 2, q = lane & 3;
        const int k0 = ks * 16 + 2 * q;
        #pragma unroll
        for (int tile = 0; tile < 2; ++tile) {
            const int hA = mt * 32 + tile * 16 + g;
            const int hB = hA + 8;
            const int hh[4] = {hA, hB, hA, hB};
            const int kk[4] = {k0, k0, k0 + 8, k0 + 8};
            float v[8];
            #pragma unroll
            for (int r = 0; r < 4; ++r) {
                v[2*r]   = (kk[r]     < 99) ? Wc1[hh[r] * 99 + kk[r]]     : 0.0f;
                v[2*r+1] = (kk[r] + 1 < 99) ? Wc1[hh[r] * 99 + kk[r] + 1] : 0.0f;
            }
            uint32_t hi[4], lo[4];
            #pragma unroll
            for (int r = 0; r < 4; ++r) split_pack(v[2*r], v[2*r+1], hi[r], lo[r]);
            *(uint4*)(chunk + (((ks * 4 + 0 + tile) * 32) + lane) * 16) =
                make_uint4(hi[0], hi[1], hi[2], hi[3]);
            *(uint4*)(chunk + (((ks * 4 + 2 + tile) * 32) + lane) * 16) =
                make_uint4(lo[0], lo[1], lo[2], lo[3]);
        }
    } else {
        const int hl = tid - 224;
        const int h = mt * 32 + hl;
        *(float4*)(chunk + AFRAG + hl * 16) =
            make_float4(bc1[h], Wc2[h * 3], Wc2[h * 3 + 1], Wc2[h * 3 + 2]);
    }
}

// ---------------------------------------------------------------------------
// Kernel B: projection + person matching + scores for all 4 ref views.
// One block per (b,p); thread = depth bin d.
// ---------------------------------------------------------------------------
__global__ __launch_bounds__(128) void k_match(
    const float* __restrict__ kpts, const float* __restrict__ joint_vis,
    const float* __restrict__ cam_R, const float* __restrict__ cam_T,
    const float* __restrict__ cam_f, const float* __restrict__ cam_c,
    const float* __restrict__ image_wh, const int* __restrict__ num_persons,
    const int* __restrict__ bones)
{
    __shared__ float s_pr[NP * NJ * 2];
    __shared__ float s_vr[NP * NJ];
    __shared__ float s_rough[NJ];
    __shared__ float s_uvn[NJ * 2];
    __shared__ float s_R0[9], s_T0[3];
    __shared__ float s_Rr[9], s_Tr[3], s_fr[2], s_cr[2], s_wh[2];
    __shared__ int   s_bones[NBONES * 2];
    __shared__ float s_p2t[128 * 35];

    const int n = blockIdx.x;
    const int b = n / NP, p = n % NP;
    const int d = threadIdx.x;

    if (d < NJ) s_rough[d] = g_rough[n * NJ + d];
    if (d < 9)  s_R0[d] = cam_R[(0 * NB_ + b) * 9 + d];
    if (d < 3)  s_T0[d] = cam_T[(0 * NB_ + b) * 3 + d];
    if (d >= 32 && d < 32 + NBONES * 2) s_bones[d - 32] = bones[d - 32];
    if (d >= 64 && d < 64 + NJ * 2) {
        int m = d - 64;
        int c = m & 1;
        float cc = cam_c[(0 * NB_ + b) * 2 + c];
        float ff = cam_f[(0 * NB_ + b) * 2 + c];
        s_uvn[m] = (kpts[(((0 * NB_ + b) * NP + p) * NJ) * 2 + m] - cc) / ff;
    }

    float sc[NJ], bd[NJ], sc2[NBONES], bd2[NBONES];
    #pragma unroll
    for (int j = 0; j < NJ; ++j) { sc[j] = 0.0f; bd[j] = 0.0f; }
    #pragma unroll
    for (int e = 0; e < NBONES; ++e) { sc2[e] = 0.0f; bd2[e] = 0.0f; }

    const float label = ((float)d / 127.0f) * 6000.0f + 2000.0f;

    for (int rv = 1; rv < NV; ++rv) {
        __syncthreads();
        const int cambase = rv * NB_ + b;
        {
            const float* src = kpts + (size_t)cambase * NP * NJ * 2;
            for (int idx = d; idx < NP * NJ * 2; idx += 128) s_pr[idx] = src[idx];
            const float* vsrc = joint_vis + (size_t)cambase * NP * NJ;
            for (int idx = d; idx < NP * NJ; idx += 128) s_vr[idx] = vsrc[idx];
            if (d < 9) s_Rr[d] = cam_R[cambase * 9 + d];
            if (d < 3) s_Tr[d] = cam_T[cambase * 3 + d];
            if (d < 2) {
                s_fr[d] = cam_f[cambase * 2 + d];
                s_cr[d] = cam_c[cambase * 2 + d];
                s_wh[d] = image_wh[cambase * 2 + d];
            }
        }
        __syncthreads();
        const int np_r = num_persons[rv * NB_ + b];

        float px[NJ], py[NJ];
        #pragma unroll
        for (int j = 0; j < NJ; ++j) {
            float z  = label + s_rough[j];
            float cx = s_uvn[2 * j] * z;
            float cy = s_uvn[2 * j + 1] * z;
            float p0 = s_R0[0] * cx + s_R0[3] * cy + s_R0[6] * z + s_T0[0];
            float p1 = s_R0[1] * cx + s_R0[4] * cy + s_R0[7] * z + s_T0[1];
            float p2 = s_R0[2] * cx + s_R0[5] * cy + s_R0[8] * z + s_T0[2];
            float q0 = p0 - s_Tr[0], q1 = p1 - s_Tr[1], q2 = p2 - s_Tr[2];
            float xc0 = s_Rr[0] * q0 + s_Rr[1] * q1 + s_Rr[2] * q2;
            float xc1 = s_Rr[3] * q0 + s_Rr[4] * q1 + s_Rr[5] * q2;
            float xc2 = s_Rr[6] * q0 + s_Rr[7] * q1 + s_Rr[8] * q2;
            float inv = 1.0f / (xc2 + 1e-8f);
            px[j] = xc0 * inv * s_fr[0] + s_cr[0];
            py[j] = xc1 * inv * s_fr[1] + s_cr[1];
            s_p2t[d * 35 + 2 * j]     = px[j];
            s_p2t[d * 35 + 2 * j + 1] = py[j];
        }

        // argmin over candidate persons (exact math; first-min semantics)
        float best = 3.4e38f; int mm = 0;
        for (int q = 0; q < NP; ++q) {
            float num = 0.0f, den = 0.0f;
            #pragma unroll
            for (int j = 0; j < NJ; ++j) {
                float w  = s_vr[q * NJ + j];
                float dx = px[j] - s_pr[(q * NJ + j) * 2];
                float dy = py[j] - s_pr[(q * NJ + j) * 2 + 1];
                num += w * (dx * dx + dy * dy);
                den += w;
            }
            float val = num / (den + 1e-8f);
            if (q >= np_r) val = 100000.0f;
            if (val < best) { best = val; mm = q; }
        }

        const int mbase = mm * NJ;
        #pragma unroll
        for (int j = 0; j < NJ; ++j) {
            float mx = s_pr[(mbase + j) * 2];
            float my = s_pr[(mbase + j) * 2 + 1];
            float mv = s_vr[mbase + j];
            float dx = px[j] - mx, dy = py[j] - my;
            float score = __expf(-fsqrt_ap(dx * dx + dy * dy + 1e-12f) * 0.01f);
            float inb = (px[j] >= 0.0f && py[j] >= 0.0f &&
                         px[j] <= s_wh[0] - 1.0f && py[j] <= s_wh[1] - 1.0f) ? 1.0f : 0.0f;
            float bnd = inb * mv;
            sc[j] += score * bnd;
            bd[j] += bnd;
        }

        const float b20 = s_vr[mbase + 0];
        #pragma unroll
        for (int e = 0; e < NBONES; ++e) {
            int a = s_bones[2 * e], bb = s_bones[2 * e + 1];
            float pax = s_p2t[d * 35 + 2 * a], pay = s_p2t[d * 35 + 2 * a + 1];
            float pbx = s_p2t[d * 35 + 2 * bb], pby = s_p2t[d * 35 + 2 * bb + 1];
            float dxp = pax - pbx, dyp = pay - pby;
            float blp = fsqrt_ap(dxp * dxp + dyp * dyp + 1e-12f);
            float max_ = s_pr[(mbase + a) * 2],  may_ = s_pr[(mbase + a) * 2 + 1];
            float mbx_ = s_pr[(mbase + bb) * 2], mby_ = s_pr[(mbase + bb) * 2 + 1];
            float dxm = max_ - mbx_, dym = may_ - mby_;
            float blm = fsqrt_ap(dxm * dxm + dym * dym + 1e-12f);
            float sbl = __expf(-fabsf(blm - blp) * 0.2f);
            sc2[e] += sbl * b20;
            bd2[e] += b20;
        }
    }

    float* xrow = g_xin + (size_t)n * NC * ND;
    #pragma unroll
    for (int j = 0; j < NJ; ++j)
        xrow[j * ND + d] = sc[j] / (bd[j] + 1e-8f);
    #pragma unroll
    for (int e = 0; e < NBONES; ++e)
        xrow[(NJ + e) * ND + d] = sc2[e] / (bd2[e] + 1e-8f);
}

// ---------------------------------------------------------------------------
// Kernel C: conv1 bf16-split GEMM (mma.sync, 2 CTA/SM) + register-resident
// conv2 + softmax + masked expectation.  One block (256 thr, 8 warps) per n.
// Warp w owns t in [16w,16w+16) for ALL 1024 h (32 M32 steps).
// B (X) fragments resident in 56 regs; A streamed via cp.async 2-deep pipe.
// ---------------------------------------------------------------------------
__global__ __launch_bounds__(256, 2) void k_conv_tc(
    const float* __restrict__ bc2, float* __restrict__ out)
{
    extern __shared__ __align__(16) unsigned char smem_raw[];
    __shared__ float sER[8], sEL[8];
    __shared__ float s_logit[ND];
    __shared__ float s_red[ND];

    const int n   = blockIdx.x;
    const int tid = threadIdx.x;
    const int w    = tid >> 5;
    const int lane = tid & 31;
    const int g = lane >> 2, q = lane & 3;

    const uint32_t sbase = smem_u32(smem_raw);
    const uint32_t xhi = sbase;
    const uint32_t xlo = sbase + XBYTES;

    // ---- build im2col X (t-major, bf16 hi/lo k-pairs) ----
    {
        const float* src = g_xin + (size_t)n * NC * ND;
        for (int idx = tid; idx < 128 * 64; idx += 256) {
            const int kp = idx & 63;
            if (kp >= 56) continue;
            const int t = idx >> 6;
            const int k0 = 2 * kp;
            float v0 = 0.0f, v1 = 0.0f;
            if (k0 < 99) {
                int c = k0 / 3, tap = k0 - 3 * c;
                int tt = t + tap - 1;
                if (tt >= 0 && tt < ND) v0 = src[c * ND + tt];
            }
            if (k0 + 1 < 99) {
                int c = (k0 + 1) / 3, tap = (k0 + 1) - 3 * c;
                int tt = t + tap - 1;
                if (tt >= 0 && tt < ND) v1 = src[c * ND + tt];
            }
            uint32_t hi, lo;
            split_pack(v0, v1, hi, lo);
            const uint32_t off = (uint32_t)t * XROW + (uint32_t)kp * 4;
            asm volatile("st.shared.b32 [%0], %1;" :: "r"(xhi + off), "r"(hi) : "memory");
            asm volatile("st.shared.b32 [%0], %1;" :: "r"(xlo + off), "r"(lo) : "memory");
        }
    }

    // ---- prefetch A chunks 0,1 ----
    {
        for (int i = tid; i < ACHUNK / 16; i += 256)
            cp16(sbase + 2 * XBYTES + i * 16, g_Wst + i * 16);
        cp_commit();
        for (int i = tid; i < ACHUNK / 16; i += 256)
            cp16(sbase + 2 * XBYTES + ACHUNK + i * 16, g_Wst + ACHUNK + i * 16);
        cp_commit();
    }
    __syncthreads();   // X visible

    // ---- load resident B fragments (all 7 k-steps for this warp's 16 t) ----
    uint32_t bh[NKS][4], bl[NKS][4];
    {
        const int seg = lane >> 3, rs = lane & 7;
        const int t = 16 * w + ((seg & 2) << 2) + rs;   // +8 rows for seg 2,3
        const uint32_t kbyte = (uint32_t)(seg & 1) * 16u;
        #pragma unroll
        for (int ks = 0; ks < NKS; ++ks) {
            const uint32_t a = xhi + (uint32_t)t * XROW + (uint32_t)ks * 32 + kbyte;
            ldsm4(bh[ks], a);
            ldsm4(bl[ks], a + XBYTES);
        }
    }

    float P0 = 0.0f, P1 = 0.0f, P2 = 0.0f, P3 = 0.0f, eR = 0.0f, eL = 0.0f;

    #pragma unroll 1
    for (int mt = 0; mt < NMT; ++mt) {
        if (mt < NMT - 1) cp_wait1(); else cp_wait0();
        __syncthreads();   // chunk mt resident for all
        const uint4* sA = (const uint4*)(smem_raw + 2 * XBYTES + (mt & 1) * ACHUNK);

        float acc0[2][4], acc1[2][4];
        #pragma unroll
        for (int nt = 0; nt < 2; ++nt)
            #pragma unroll
            for (int j = 0; j < 4; ++j) { acc0[nt][j] = 0.0f; acc1[nt][j] = 0.0f; }

        #pragma unroll
        for (int ks = 0; ks < NKS; ++ks) {
            const uint4 h0 = sA[(ks * 4 + 0) * 32 + lane];
            const uint4 h1 = sA[(ks * 4 + 1) * 32 + lane];
            const uint4 l0 = sA[(ks * 4 + 2) * 32 + lane];
            const uint4 l1 = sA[(ks * 4 + 3) * 32 + lane];
            #pragma unroll
            for (int nt = 0; nt < 2; ++nt) {
                const uint32_t b0h = bh[ks][2 * nt], b1h = bh[ks][2 * nt + 1];
                const uint32_t b0l = bl[ks][2 * nt], b1l = bl[ks][2 * nt + 1];
                mma_bf16(acc0[nt], h0.x, h0.y, h0.z, h0.w, b0h, b1h);
                mma_bf16(acc0[nt], h0.x, h0.y, h0.z, h0.w, b0l, b1l);
                mma_bf16(acc0[nt], l0.x, l0.y, l0.z, l0.w, b0h, b1h);
                mma_bf16(acc1[nt], h1.x, h1.y, h1.z, h1.w, b0h, b1h);
                mma_bf16(acc1[nt], h1.x, h1.y, h1.z, h1.w, b0l, b1l);
                mma_bf16(acc1[nt], l1.x, l1.y, l1.z, l1.w, b0h, b1h);
            }
        }

        // ---- fused conv2 epilogue: 4 h-rows per lane (g, g+8, g+16, g+24) ----
        const float4* meta = (const float4*)(smem_raw + 2 * XBYTES
                                             + (mt & 1) * ACHUNK + AFRAG);
        #pragma unroll
        for (int r = 0; r < 4; ++r) {
            const float4 m = meta[g + 8 * r];
            float ya, yb, yc, yd;
            if (r == 0)      { ya = acc0[0][0]; yb = acc0[0][1]; yc = acc0[1][0]; yd = acc0[1][1]; }
            else if (r == 1) { ya = acc0[0][2]; yb = acc0[0][3]; yc = acc0[1][2]; yd = acc0[1][3]; }
            else if (r == 2) { ya = acc1[0][0]; yb = acc1[0][1]; yc = acc1[1][0]; yd = acc1[1][1]; }
            else             { ya = acc1[0][2]; yb = acc1[0][3]; yc = acc1[1][2]; yd = acc1[1][3]; }
            ya = fmaxf(ya + m.x, 0.0f);
            yb = fmaxf(yb + m.x, 0.0f);
            yc = fmaxf(yc + m.x, 0.0f);
            yd = fmaxf(yd + m.x, 0.0f);
            const float w0 = m.y, w1 = m.z, w2 = m.w;

            const float n_b = __shfl_sync(0xffffffffu, yb, lane - 1);  // y[2q-1]
            const float n_a = __shfl_sync(0xffffffffu, ya, lane + 1);  // y[2q+2]
            const float n_d = __shfl_sync(0xffffffffu, yd, lane - 1);  // y[2q+7]
            const float n_c = __shfl_sync(0xffffffffu, yc, lane + 1);  // y[2q+10]
            const float x_b = __shfl_sync(0xffffffffu, yb, lane | 3);  // y[7]
            const float x_c = __shfl_sync(0xffffffffu, yc, lane & ~3); // y[8]

            P0 += w1 * ya + w2 * yb + ((q > 0) ? w0 * n_b : 0.0f);
            P1 += w0 * ya + w1 * yb + w2 * ((q < 3) ? n_a : x_c);
            P2 += w1 * yc + w2 * yd + w0 * ((q > 0) ? n_d : x_b);
            P3 += w0 * yc + w1 * yd + ((q < 3) ? w2 * n_c : 0.0f);
            if (q == 3) eR += w0 * yd;   // -> logit[16w+16]
            if (q == 0) eL += w2 * ya;   // -> logit[16w-1]
        }

        // ---- pipeline: refill the buffer just consumed with chunk mt+2 ----
        __syncthreads();   // all warps done reading buffer (mt&1)
        if (mt + 2 < NMT) {
            const unsigned char* gsrc = g_Wst + (size_t)(mt + 2) * ACHUNK;
            const uint32_t dst = sbase + 2 * XBYTES + (uint32_t)((mt & 1) * ACHUNK);
            for (int i = tid; i < ACHUNK / 16; i += 256)
                cp16(dst + i * 16, gsrc + i * 16);
            cp_commit();
        }
    }

    // ---- reduce P over g (lane bits 2..4) ----
    #pragma unroll
    for (int off = 4; off <= 16; off <<= 1) {
        P0 += __shfl_xor_sync(0xffffffffu, P0, off);
        P1 += __shfl_xor_sync(0xffffffffu, P1, off);
        P2 += __shfl_xor_sync(0xffffffffu, P2, off);
        P3 += __shfl_xor_sync(0xffffffffu, P3, off);
    }
    // edge scalars: full-warp reduce
    #pragma unroll
    for (int off = 1; off <= 16; off <<= 1) {
        eR += __shfl_xor_sync(0xffffffffu, eR, off);
        eL += __shfl_xor_sync(0xffffffffu, eL, off);
    }
    if (lane < 4) {
        s_logit[16 * w + 2 * lane]     = P0;
        s_logit[16 * w + 2 * lane + 1] = P1;
        s_logit[16 * w + 2 * lane + 8] = P2;
        s_logit[16 * w + 2 * lane + 9] = P3;
    }
    if (lane == 0) { sER[w] = eR; sEL[w] = eL; }
    __syncthreads();

    if (tid < ND) {
        const int wt = tid >> 4, lt = tid & 15;
        float v = s_logit[tid] + bc2[0];
        if (lt == 0  && wt > 0) v += sER[wt - 1];
        if (lt == 15 && wt < 7) v += sEL[wt + 1];
        s_logit[tid] = v;
    }
    __syncthreads();

    // ---- softmax + argmax window + masked expectation ----
    if (tid < ND) s_red[tid] = s_logit[tid];
    __syncthreads();
    for (int s = 64; s > 0; s >>= 1) {
        if (tid < s) s_red[tid] = fmaxf(s_red[tid], s_red[tid + s]);
        __syncthreads();
    }
    const float mx = s_red[0];
    __syncthreads();

    if (tid < ND) s_red[tid] = (s_logit[tid] == mx) ? (float)tid : 1.0e9f;
    __syncthreads();
    for (int s = 64; s > 0; s >>= 1) {
        if (tid < s) s_red[tid] = fminf(s_red[tid], s_red[tid + s]);
        __syncthreads();
    }
    const int idx = (int)s_red[0];
    __syncthreads();

    float e = 0.0f;
    if (tid < ND) e = expf(s_logit[tid] - mx);

    if (tid < ND) s_red[tid] = e;
    __syncthreads();
    for (int s = 64; s > 0; s >>= 1) {
        if (tid < s) s_red[tid] += s_red[tid + s];
        __syncthreads();
    }
    const float S = s_red[0];
    __syncthreads();

    const float me = (tid < ND && abs(tid - idx) <= 5) ? e : 0.0f;

    if (tid < ND) s_red[tid] = me;
    __syncthreads();
    for (int s = 64; s > 0; s >>= 1) {
        if (tid < s) s_red[tid] += s_red[tid + s];
        __syncthreads();
    }
    const float den = s_red[0];
    __syncthreads();

    if (tid < ND) s_red[tid] = me * (float)tid;
    __syncthreads();
    for (int s = 64; s > 0; s >>= 1) {
        if (tid < s) s_red[tid] += s_red[tid + s];
        __syncthreads();
    }
    if (tid == 0) {
        float pred = s_red[0] / (den + 1e-8f * S);
        out[n] = pred * (6000.0f / 127.0f) + 2000.0f;
    }
}

// ---------------------------------------------------------------------------
extern "C" void kernel_launch(void* const* d_in, const int* in_sizes, int n_in,
                              void* d_out, int out_size)
{
    const float* kpts        = (const float*)d_in[0];
    const float* joint_vis   = (const float*)d_in[2];
    const float* cam_R       = (const float*)d_in[5];
    const float* cam_T       = (const float*)d_in[6];
    const float* cam_f       = (const float*)d_in[7];
    const float* cam_c       = (const float*)d_in[8];
    const float* image_wh    = (const float*)d_in[9];
    const int*   num_persons = (const int*)d_in[10];
    const float* Wr1         = (const float*)d_in[11];
    const float* br1         = (const float*)d_in[12];
    const float* Wr2         = (const float*)d_in[13];
    const float* br2         = (const float*)d_in[14];
    const float* Wc1         = (const float*)d_in[15];
    const float* bc1         = (const float*)d_in[16];
    const float* Wc2         = (const float*)d_in[17];
    const float* bc2         = (const float*)d_in[18];
    const int*   bones       = (const int*)d_in[19];
    float* out = (float*)d_out;

    cudaFuncSetAttribute(k_conv_tc, cudaFuncAttributeMaxDynamicSharedMemorySize,
                         SMEM_DYN);

    k_rough<<<NROWS, 128>>>(kpts, image_wh, Wr1, br1, Wr2, br2);
    k_repack_frag<<<NMT, 256>>>(Wc1, bc1, Wc2);
    k_match<<<NROWS, 128>>>(kpts, joint_vis, cam_R, cam_T, cam_f, cam_c,
                            image_wh, num_persons, bones);
    k_conv_tc<<<NROWS, 256, SMEM_DYN>>>(bc2, out);
}

// round 9
// speedup vs baseline: 2.8973x; 1.0485x over previous
#include <cuda_runtime.h>
#include <cuda_bf16.h>
#include <cstdint>
#include <math.h>

// Problem constants
#define NV 5
#define NB_ 32      // batch
#define NP 20
#define NJ 17
#define NBONES 16
#define ND 128
#define HR 1024
#define HID 1024
#define NROWS (NB_*NP)          // 640
#define NC (NJ + NBONES)        // 33
#define NKS 7                   // k-steps of 16 (K=112)
#define NMT 32                  // m-steps of 32 h
#define XROW 240                // X row stride in bytes (56 kpairs = 224B + pad)
#define XBYTES (128 * XROW)     // 30720
#define AFRAG  (NKS * 4 * 32 * 16)          // 14336
#define ACHUNK (AFRAG + 32 * 16)            // + meta {bc1,w0,w1,w2} = 14848
#define SMEM_DYN (2 * XBYTES)               // 61440; A ring (4*ACHUNK) reuses it

// Scratch (device globals; no runtime allocation)
__device__ float g_xin[NROWS * NC * ND];                     // (n, c, t)
__device__ __align__(16) unsigned char g_Wst[NMT * ACHUNK];  // A frags + meta

// ---------------------------------------------------------------------------
// helpers
// ---------------------------------------------------------------------------
__device__ __forceinline__ void split_pack(float v0, float v1, uint32_t& hi, uint32_t& lo) {
    __nv_bfloat16 h0 = __float2bfloat16(v0);
    __nv_bfloat16 h1 = __float2bfloat16(v1);
    float r0 = v0 - __bfloat162float(h0);
    float r1 = v1 - __bfloat162float(h1);
    __nv_bfloat16 l0 = __float2bfloat16(r0);
    __nv_bfloat16 l1 = __float2bfloat16(r1);
    hi = ((uint32_t)__bfloat16_as_ushort(h1) << 16) | (uint32_t)__bfloat16_as_ushort(h0);
    lo = ((uint32_t)__bfloat16_as_ushort(l1) << 16) | (uint32_t)__bfloat16_as_ushort(l0);
}

__device__ __forceinline__ uint32_t smem_u32(const void* p) {
    uint32_t a;
    asm("{ .reg .u64 t; cvta.to.shared.u64 t, %1; cvt.u32.u64 %0, t; }" : "=r"(a) : "l"(p));
    return a;
}

__device__ __forceinline__ void mma_bf16(float* c,
                                         uint32_t a0, uint32_t a1, uint32_t a2, uint32_t a3,
                                         uint32_t b0, uint32_t b1) {
    asm volatile("mma.sync.aligned.m16n8k16.row.col.f32.bf16.bf16.f32 "
                 "{%0,%1,%2,%3},{%4,%5,%6,%7},{%8,%9},{%0,%1,%2,%3};"
                 : "+f"(c[0]), "+f"(c[1]), "+f"(c[2]), "+f"(c[3])
                 : "r"(a0), "r"(a1), "r"(a2), "r"(a3), "r"(b0), "r"(b1));
}

__device__ __forceinline__ void ldsm4(uint32_t* r, uint32_t addr) {
    asm volatile("ldmatrix.sync.aligned.m8n8.x4.shared.b16 {%0,%1,%2,%3}, [%4];"
                 : "=r"(r[0]), "=r"(r[1]), "=r"(r[2]), "=r"(r[3]) : "r"(addr));
}

__device__ __forceinline__ void cp16(uint32_t s, const void* g) {
    asm volatile("cp.async.cg.shared.global [%0], [%1], 16;" :: "r"(s), "l"(g));
}
__device__ __forceinline__ void cp_commit() { asm volatile("cp.async.commit_group;" ::: "memory"); }
__device__ __forceinline__ void cp_wait2()  { asm volatile("cp.async.wait_group 2;" ::: "memory"); }
__device__ __forceinline__ void cp_wait1()  { asm volatile("cp.async.wait_group 1;" ::: "memory"); }
__device__ __forceinline__ void cp_wait0()  { asm volatile("cp.async.wait_group 0;" ::: "memory"); }

__device__ __forceinline__ float fsqrt_ap(float x) {
    float r; asm("sqrt.approx.f32 %0, %1;" : "=f"(r) : "f"(x)); return r;
}

// ---------------------------------------------------------------------------
// Kernel W: pack conv1 weights into per-mt A-fragment chunks + meta.
// chunk mt layout: [ks 7][part 4][lane 32] uint4  (part: 0=hi tile0, 1=hi
// tile1, 2=lo tile0, 3=lo tile1), then [hl 32] float4 {bc1, w0, w1, w2}.
// ---------------------------------------------------------------------------
__global__ __launch_bounds__(256) void k_repack_frag(
    const float* __restrict__ Wc1, const float* __restrict__ bc1,
    const float* __restrict__ Wc2)
{
    const int mt  = blockIdx.x;
    const int tid = threadIdx.x;
    unsigned char* chunk = g_Wst + (size_t)mt * ACHUNK;

    if (tid < 224) {
        const int ks = tid >> 5, lane = tid & 31;
        const int g = lane >> 2, q = lane & 3;
        const int k0 = ks * 16 + 2 * q;
        #pragma unroll
        for (int tile = 0; tile < 2; ++tile) {
            const int hA = mt * 32 + tile * 16 + g;
            const int hB = hA + 8;
            const int hh[4] = {hA, hB, hA, hB};
            const int kk[4] = {k0, k0, k0 + 8, k0 + 8};
            float v[8];
            #pragma unroll
            for (int r = 0; r < 4; ++r) {
                v[2*r]   = (kk[r]     < 99) ? Wc1[hh[r] * 99 + kk[r]]     : 0.0f;
                v[2*r+1] = (kk[r] + 1 < 99) ? Wc1[hh[r] * 99 + kk[r] + 1] : 0.0f;
            }
            uint32_t hi[4], lo[4];
            #pragma unroll
            for (int r = 0; r < 4; ++r) split_pack(v[2*r], v[2*r+1], hi[r], lo[r]);
            *(uint4*)(chunk + (((ks * 4 + 0 + tile) * 32) + lane) * 16) =
                make_uint4(hi[0], hi[1], hi[2], hi[3]);
            *(uint4*)(chunk + (((ks * 4 + 2 + tile) * 32) + lane) * 16) =
                make_uint4(lo[0], lo[1], lo[2], lo[3]);
        }
    } else {
        const int hl = tid - 224;
        const int h = mt * 32 + hl;
        *(float4*)(chunk + AFRAG + hl * 16) =
            make_float4(bc1[h], Wc2[h * 3], Wc2[h * 3 + 1], Wc2[h * 3 + 2]);
    }
}

// ---------------------------------------------------------------------------
// Kernel B: rough MLP + projection + matching + scores (all fused).
// One block per (b,p); thread = depth bin d.
// ---------------------------------------------------------------------------
__global__ __launch_bounds__(128) void k_match(
    const float* __restrict__ kpts, const float* __restrict__ joint_vis,
    const float* __restrict__ cam_R, const float* __restrict__ cam_T,
    const float* __restrict__ cam_f, const float* __restrict__ cam_c,
    const float* __restrict__ image_wh, const int* __restrict__ num_persons,
    const int* __restrict__ bones,
    const float* __restrict__ Wr1, const float* __restrict__ br1,
    const float* __restrict__ Wr2, const float* __restrict__ br2)
{
    __shared__ float xs[NJ * 2];
    __shared__ float hs[HR];
    __shared__ float s_pr[NP * NJ * 2];
    __shared__ float s_vr[NP * NJ];
    __shared__ float s_rough[NJ];
    __shared__ float s_uvn[NJ * 2];
    __shared__ float s_R0[9], s_T0[3];
    __shared__ float s_Rr[9], s_Tr[3], s_fr[2], s_cr[2], s_wh[2];
    __shared__ int   s_bones[NBONES * 2];
    __shared__ float s_p2t[128 * 35];
    __shared__ float4 s_q4[NP * NJ];
    __shared__ float s_base[NP], s_den[NP];

    const int n = blockIdx.x;
    const int b = n / NP, p = n % NP;
    const int d = threadIdx.x;

    // ---- static loads + rough-MLP input ----
    if (d < NJ * 2)
        xs[d] = kpts[(((0 * NB_ + b) * NP + p) * NJ) * 2 + d] / image_wh[d & 1];
    if (d < 9)  s_R0[d] = cam_R[(0 * NB_ + b) * 9 + d];
    if (d < 3)  s_T0[d] = cam_T[(0 * NB_ + b) * 3 + d];
    if (d >= 32 && d < 32 + NBONES * 2) s_bones[d - 32] = bones[d - 32];
    if (d >= 64 && d < 64 + NJ * 2) {
        int m = d - 64;
        int c = m & 1;
        float cc = cam_c[(0 * NB_ + b) * 2 + c];
        float ff = cam_f[(0 * NB_ + b) * 2 + c];
        s_uvn[m] = (kpts[(((0 * NB_ + b) * NP + p) * NJ) * 2 + m] - cc) / ff;
    }
    __syncthreads();

    // ---- rough MLP (fused) ----
    for (int i = d; i < HR; i += 128) {
        const float* wr = Wr1 + i * (NJ * 2);
        float acc = br1[i];
        #pragma unroll
        for (int m = 0; m < NJ * 2; ++m) acc += wr[m] * xs[m];
        hs[i] = fmaxf(acc, 0.0f);
    }
    __syncthreads();
    {
        const int warp = d >> 5, lane = d & 31;
        for (int j = warp; j < NJ; j += 4) {
            const float* wr = Wr2 + j * HR;
            float acc = 0.0f;
            for (int i = lane; i < HR; i += 32) acc += hs[i] * wr[i];
            #pragma unroll
            for (int off = 16; off > 0; off >>= 1)
                acc += __shfl_down_sync(0xffffffffu, acc, off);
            if (lane == 0) s_rough[j] = (acc + br2[j]) * 1000.0f;
        }
    }

    float sc[NJ], bd[NJ], sc2[NBONES], bd2[NBONES];
    #pragma unroll
    for (int j = 0; j < NJ; ++j) { sc[j] = 0.0f; bd[j] = 0.0f; }
    #pragma unroll
    for (int e = 0; e < NBONES; ++e) { sc2[e] = 0.0f; bd2[e] = 0.0f; }

    const float label = ((float)d / 127.0f) * 6000.0f + 2000.0f;

    for (int rv = 1; rv < NV; ++rv) {
        __syncthreads();
        const int cambase = rv * NB_ + b;
        {
            const float* src = kpts + (size_t)cambase * NP * NJ * 2;
            for (int idx = d; idx < NP * NJ * 2; idx += 128) s_pr[idx] = src[idx];
            const float* vsrc = joint_vis + (size_t)cambase * NP * NJ;
            for (int idx = d; idx < NP * NJ; idx += 128) s_vr[idx] = vsrc[idx];
            if (d < 9) s_Rr[d] = cam_R[cambase * 9 + d];
            if (d < 3) s_Tr[d] = cam_T[cambase * 3 + d];
            if (d < 2) {
                s_fr[d] = cam_f[cambase * 2 + d];
                s_cr[d] = cam_c[cambase * 2 + d];
                s_wh[d] = image_wh[cambase * 2 + d];
            }
        }
        __syncthreads();
        // per-view precompute for expanded-distance argmin
        for (int idx = d; idx < NP * NJ; idx += 128) {
            float w   = s_vr[idx];
            float prx = s_pr[2 * idx];
            float pry = s_pr[2 * idx + 1];
            s_q4[idx] = make_float4(w, 2.0f * w * prx, 2.0f * w * pry,
                                    w * (prx * prx + pry * pry));
        }
        __syncthreads();
        if (d < NP) {
            float bs = 0.0f, dn = 0.0f;
            #pragma unroll
            for (int j = 0; j < NJ; ++j) {
                bs += s_q4[d * NJ + j].w;
                dn += s_q4[d * NJ + j].x;
            }
            s_base[d] = bs; s_den[d] = dn;
        }
        __syncthreads();
        const int np_r = num_persons[rv * NB_ + b];

        float px[NJ], py[NJ], s2[NJ];
        #pragma unroll
        for (int j = 0; j < NJ; ++j) {
            float z  = label + s_rough[j];
            float cx = s_uvn[2 * j] * z;
            float cy = s_uvn[2 * j + 1] * z;
            float p0 = s_R0[0] * cx + s_R0[3] * cy + s_R0[6] * z + s_T0[0];
            float p1 = s_R0[1] * cx + s_R0[4] * cy + s_R0[7] * z + s_T0[1];
            float p2 = s_R0[2] * cx + s_R0[5] * cy + s_R0[8] * z + s_T0[2];
            float q0 = p0 - s_Tr[0], q1 = p1 - s_Tr[1], q2 = p2 - s_Tr[2];
            float xc0 = s_Rr[0] * q0 + s_Rr[1] * q1 + s_Rr[2] * q2;
            float xc1 = s_Rr[3] * q0 + s_Rr[4] * q1 + s_Rr[5] * q2;
            float xc2 = s_Rr[6] * q0 + s_Rr[7] * q1 + s_Rr[8] * q2;
            float inv = 1.0f / (xc2 + 1e-8f);
            px[j] = xc0 * inv * s_fr[0] + s_cr[0];
            py[j] = xc1 * inv * s_fr[1] + s_cr[1];
            s2[j] = px[j] * px[j] + py[j] * py[j];
            s_p2t[d * 35 + 2 * j]     = px[j];
            s_p2t[d * 35 + 2 * j + 1] = py[j];
        }

        // argmin via expanded distance (near-min candidates unambiguous)
        float best = 3.4e38f; int mm = 0;
        for (int q = 0; q < NP; ++q) {
            float num = s_base[q];
            #pragma unroll
            for (int j = 0; j < NJ; ++j) {
                float4 f = s_q4[q * NJ + j];
                num = fmaf(f.x, s2[j], num);
                num = fmaf(-f.y, px[j], num);
                num = fmaf(-f.z, py[j], num);
            }
            float val = __fdividef(num, s_den[q] + 1e-8f);
            if (q >= np_r) val = 100000.0f;
            if (val < best) { best = val; mm = q; }
        }

        const int mbase = mm * NJ;
        #pragma unroll
        for (int j = 0; j < NJ; ++j) {
            float mx = s_pr[(mbase + j) * 2];
            float my = s_pr[(mbase + j) * 2 + 1];
            float mv = s_vr[mbase + j];
            float dx = px[j] - mx, dy = py[j] - my;
            float score = __expf(-fsqrt_ap(dx * dx + dy * dy + 1e-12f) * 0.01f);
            float inb = (px[j] >= 0.0f && py[j] >= 0.0f &&
                         px[j] <= s_wh[0] - 1.0f && py[j] <= s_wh[1] - 1.0f) ? 1.0f : 0.0f;
            float bnd = inb * mv;
            sc[j] += score * bnd;
            bd[j] += bnd;
        }

        const float b20 = s_vr[mbase + 0];
        #pragma unroll
        for (int e = 0; e < NBONES; ++e) {
            int a = s_bones[2 * e], bb = s_bones[2 * e + 1];
            float pax = s_p2t[d * 35 + 2 * a], pay = s_p2t[d * 35 + 2 * a + 1];
            float pbx = s_p2t[d * 35 + 2 * bb], pby = s_p2t[d * 35 + 2 * bb + 1];
            float dxp = pax - pbx, dyp = pay - pby;
            float blp = fsqrt_ap(dxp * dxp + dyp * dyp + 1e-12f);
            float max_ = s_pr[(mbase + a) * 2],  may_ = s_pr[(mbase + a) * 2 + 1];
            float mbx_ = s_pr[(mbase + bb) * 2], mby_ = s_pr[(mbase + bb) * 2 + 1];
            float dxm = max_ - mbx_, dym = may_ - mby_;
            float blm = fsqrt_ap(dxm * dxm + dym * dym + 1e-12f);
            float sbl = __expf(-fabsf(blm - blp) * 0.2f);
            sc2[e] += sbl * b20;
            bd2[e] += b20;
        }
    }

    float* xrow = g_xin + (size_t)n * NC * ND;
    #pragma unroll
    for (int j = 0; j < NJ; ++j)
        xrow[j * ND + d] = sc[j] / (bd[j] + 1e-8f);
    #pragma unroll
    for (int e = 0; e < NBONES; ++e)
        xrow[(NJ + e) * ND + d] = sc2[e] / (bd2[e] + 1e-8f);
}

// ---------------------------------------------------------------------------
// Kernel C: conv1 bf16-split GEMM (mma.sync, 2 CTA/SM) + register-resident
// conv2 + softmax + masked expectation.  One block (256 thr, 8 warps) per n.
// Warp w owns t in [16w,16w+16) for ALL 1024 h (32 M32 steps).
// B (X) fragments resident in 56 regs.  A streamed via a 4-slot cp.async
// ring that REUSES the X smem (X is dead after the one-time ldmatrix).
// One barrier per iteration; prefetch runs 3 chunks ahead.
// ---------------------------------------------------------------------------
__global__ __launch_bounds__(256, 2) void k_conv_tc(
    const float* __restrict__ bc2, float* __restrict__ out)
{
    extern __shared__ __align__(16) unsigned char smem_raw[];
    __shared__ float sER[8], sEL[8];
    __shared__ float s_logit[ND];
    __shared__ float s_red[ND];

    const int n   = blockIdx.x;
    const int tid = threadIdx.x;
    const int w    = tid >> 5;
    const int lane = tid & 31;
    const int g = lane >> 2, q = lane & 3;

    const uint32_t sbase = smem_u32(smem_raw);
    const uint32_t xhi = sbase;
    const uint32_t xlo = sbase + XBYTES;

    // ---- build im2col X (t-major, bf16 hi/lo k-pairs) ----
    {
        const float* src = g_xin + (size_t)n * NC * ND;
        for (int idx = tid; idx < 128 * 64; idx += 256) {
            const int kp = idx & 63;
            if (kp >= 56) continue;
            const int t = idx >> 6;
            const int k0 = 2 * kp;
            float v0 = 0.0f, v1 = 0.0f;
            if (k0 < 99) {
                int c = k0 / 3, tap = k0 - 3 * c;
                int tt = t + tap - 1;
                if (tt >= 0 && tt < ND) v0 = src[c * ND + tt];
            }
            if (k0 + 1 < 99) {
                int c = (k0 + 1) / 3, tap = (k0 + 1) - 3 * c;
                int tt = t + tap - 1;
                if (tt >= 0 && tt < ND) v1 = src[c * ND + tt];
            }
            uint32_t hi, lo;
            split_pack(v0, v1, hi, lo);
            const uint32_t off = (uint32_t)t * XROW + (uint32_t)kp * 4;
            asm volatile("st.shared.b32 [%0], %1;" :: "r"(xhi + off), "r"(hi) : "memory");
            asm volatile("st.shared.b32 [%0], %1;" :: "r"(xlo + off), "r"(lo) : "memory");
        }
    }
    __syncthreads();   // X visible

    // ---- load resident B fragments (all 7 k-steps for this warp's 16 t) ----
    uint32_t bh[NKS][4], bl[NKS][4];
    {
        const int seg = lane >> 3, rs = lane & 7;
        const int t = 16 * w + ((seg & 2) << 2) + rs;   // +8 rows for seg 2,3
        const uint32_t kbyte = (uint32_t)(seg & 1) * 16u;
        #pragma unroll
        for (int ks = 0; ks < NKS; ++ks) {
            const uint32_t a = xhi + (uint32_t)t * XROW + (uint32_t)ks * 32 + kbyte;
            ldsm4(bh[ks], a);
            ldsm4(bl[ks], a + XBYTES);
        }
    }
    __syncthreads();   // all ldsm done -> X region reusable as A ring

    // ---- prologue: chunks 0,1,2 into ring slots 0,1,2 ----
    #pragma unroll
    for (int c = 0; c < 3; ++c) {
        const unsigned char* gsrc = g_Wst + (size_t)c * ACHUNK;
        const uint32_t dst = sbase + (uint32_t)(c * ACHUNK);
        for (int i = tid; i < ACHUNK / 16; i += 256) cp16(dst + i * 16, gsrc + i * 16);
        cp_commit();
    }

    float P0 = 0.0f, P1 = 0.0f, P2 = 0.0f, P3 = 0.0f, eR = 0.0f, eL = 0.0f;

    #pragma unroll 1
    for (int mt = 0; mt < NMT; ++mt) {
        if (mt < NMT - 2) cp_wait2();
        else if (mt == NMT - 2) cp_wait1();
        else cp_wait0();
        __syncthreads();   // chunk mt resident; slot (mt+3)&3 readers done

        // prefetch chunk mt+3 into slot (mt+3)&3 (read last at iter mt-1)
        if (mt + 3 < NMT) {
            const unsigned char* gsrc = g_Wst + (size_t)(mt + 3) * ACHUNK;
            const uint32_t dst = sbase + (uint32_t)(((mt + 3) & 3) * ACHUNK);
            for (int i = tid; i < ACHUNK / 16; i += 256) cp16(dst + i * 16, gsrc + i * 16);
            cp_commit();
        }

        const uint4* sA = (const uint4*)(smem_raw + (mt & 3) * ACHUNK);

        float acc0[2][4], acc1[2][4];
        #pragma unroll
        for (int nt = 0; nt < 2; ++nt)
            #pragma unroll
            for (int j = 0; j < 4; ++j) { acc0[nt][j] = 0.0f; acc1[nt][j] = 0.0f; }

        #pragma unroll
        for (int ks = 0; ks < NKS; ++ks) {
            const uint4 h0 = sA[(ks * 4 + 0) * 32 + lane];
            const uint4 h1 = sA[(ks * 4 + 1) * 32 + lane];
            const uint4 l0 = sA[(ks * 4 + 2) * 32 + lane];
            const uint4 l1 = sA[(ks * 4 + 3) * 32 + lane];
            #pragma unroll
            for (int nt = 0; nt < 2; ++nt) {
                const uint32_t b0h = bh[ks][2 * nt], b1h = bh[ks][2 * nt + 1];
                const uint32_t b0l = bl[ks][2 * nt], b1l = bl[ks][2 * nt + 1];
                mma_bf16(acc0[nt], h0.x, h0.y, h0.z, h0.w, b0h, b1h);
                mma_bf16(acc0[nt], h0.x, h0.y, h0.z, h0.w, b0l, b1l);
                mma_bf16(acc0[nt], l0.x, l0.y, l0.z, l0.w, b0h, b1h);
                mma_bf16(acc1[nt], h1.x, h1.y, h1.z, h1.w, b0h, b1h);
                mma_bf16(acc1[nt], h1.x, h1.y, h1.z, h1.w, b0l, b1l);
                mma_bf16(acc1[nt], l1.x, l1.y, l1.z, l1.w, b0h, b1h);
            }
        }

        // ---- fused conv2 epilogue: 4 h-rows per lane (g, g+8, g+16, g+24) ----
        const float4* meta = (const float4*)(smem_raw + (mt & 3) * ACHUNK + AFRAG);
        #pragma unroll
        for (int r = 0; r < 4; ++r) {
            const float4 m = meta[g + 8 * r];
            float ya, yb, yc, yd;
            if (r == 0)      { ya = acc0[0][0]; yb = acc0[0][1]; yc = acc0[1][0]; yd = acc0[1][1]; }
            else if (r == 1) { ya = acc0[0][2]; yb = acc0[0][3]; yc = acc0[1][2]; yd = acc0[1][3]; }
            else if (r == 2) { ya = acc1[0][0]; yb = acc1[0][1]; yc = acc1[1][0]; yd = acc1[1][1]; }
            else             { ya = acc1[0][2]; yb = acc1[0][3]; yc = acc1[1][2]; yd = acc1[1][3]; }
            ya = fmaxf(ya + m.x, 0.0f);
            yb = fmaxf(yb + m.x, 0.0f);
            yc = fmaxf(yc + m.x, 0.0f);
            yd = fmaxf(yd + m.x, 0.0f);
            const float w0 = m.y, w1 = m.z, w2 = m.w;

            const float n_b = __shfl_sync(0xffffffffu, yb, lane - 1);  // y[2q-1]
            const float n_a = __shfl_sync(0xffffffffu, ya, lane + 1);  // y[2q+2]
            const float n_d = __shfl_sync(0xffffffffu, yd, lane - 1);  // y[2q+7]
            const float n_c = __shfl_sync(0xffffffffu, yc, lane + 1);  // y[2q+10]
            const float x_b = __shfl_sync(0xffffffffu, yb, lane | 3);  // y[7]
            const float x_c = __shfl_sync(0xffffffffu, yc, lane & ~3); // y[8]

            P0 += w1 * ya + w2 * yb + ((q > 0) ? w0 * n_b : 0.0f);
            P1 += w0 * ya + w1 * yb + w2 * ((q < 3) ? n_a : x_c);
            P2 += w1 * yc + w2 * yd + w0 * ((q > 0) ? n_d : x_b);
            P3 += w0 * yc + w1 * yd + ((q < 3) ? w2 * n_c : 0.0f);
            if (q == 3) eR += w0 * yd;   // -> logit[16w+16]
            if (q == 0) eL += w2 * ya;   // -> logit[16w-1]
        }
    }

    // ---- reduce P over g (lane bits 2..4) ----
    #pragma unroll
    for (int off = 4; off <= 16; off <<= 1) {
        P0 += __shfl_xor_sync(0xffffffffu, P0, off);
        P1 += __shfl_xor_sync(0xffffffffu, P1, off);
        P2 += __shfl_xor_sync(0xffffffffu, P2, off);
        P3 += __shfl_xor_sync(0xffffffffu, P3, off);
    }
    // edge scalars: full-warp reduce
    #pragma unroll
    for (int off = 1; off <= 16; off <<= 1) {
        eR += __shfl_xor_sync(0xffffffffu, eR, off);
        eL += __shfl_xor_sync(0xffffffffu, eL, off);
    }
    if (lane < 4) {
        s_logit[16 * w + 2 * lane]     = P0;
        s_logit[16 * w + 2 * lane + 1] = P1;
        s_logit[16 * w + 2 * lane + 8] = P2;
        s_logit[16 * w + 2 * lane + 9] = P3;
    }
    if (lane == 0) { sER[w] = eR; sEL[w] = eL; }
    __syncthreads();

    if (tid < ND) {
        const int wt = tid >> 4, lt = tid & 15;
        float v = s_logit[tid] + bc2[0];
        if (lt == 0  && wt > 0) v += sER[wt - 1];
        if (lt == 15 && wt < 7) v += sEL[wt + 1];
        s_logit[tid] = v;
    }
    __syncthreads();

    // ---- softmax + argmax window + masked expectation ----
    if (tid < ND) s_red[tid] = s_logit[tid];
    __syncthreads();
    for (int s = 64; s > 0; s >>= 1) {
        if (tid < s) s_red[tid] = fmaxf(s_red[tid], s_red[tid + s]);
        __syncthreads();
    }
    const float mx = s_red[0];
    __syncthreads();

    if (tid < ND) s_red[tid] = (s_logit[tid] == mx) ? (float)tid : 1.0e9f;
    __syncthreads();
    for (int s = 64; s > 0; s >>= 1) {
        if (tid < s) s_red[tid] = fminf(s_red[tid], s_red[tid + s]);
        __syncthreads();
    }
    const int idx = (int)s_red[0];
    __syncthreads();

    float e = 0.0f;
    if (tid < ND) e = expf(s_logit[tid] - mx);

    if (tid < ND) s_red[tid] = e;
    __syncthreads();
    for (int s = 64; s > 0; s >>= 1) {
        if (tid < s) s_red[tid] += s_red[tid + s];
        __syncthreads();
    }
    const float S = s_red[0];
    __syncthreads();

    const float me = (tid < ND && abs(tid - idx) <= 5) ? e : 0.0f;

    if (tid < ND) s_red[tid] = me;
    __syncthreads();
    for (int s = 64; s > 0; s >>= 1) {
        if (tid < s) s_red[tid] += s_red[tid + s];
        __syncthreads();
    }
    const float den = s_red[0];
    __syncthreads();

    if (tid < ND) s_red[tid] = me * (float)tid;
    __syncthreads();
    for (int s = 64; s > 0; s >>= 1) {
        if (tid < s) s_red[tid] += s_red[tid + s];
        __syncthreads();
    }
    if (tid == 0) {
        float pred = s_red[0] / (den + 1e-8f * S);
        out[n] = pred * (6000.0f / 127.0f) + 2000.0f;
    }
}

// ---------------------------------------------------------------------------
extern "C" void kernel_launch(void* const* d_in, const int* in_sizes, int n_in,
                              void* d_out, int out_size)
{
    const float* kpts        = (const float*)d_in[0];
    const float* joint_vis   = (const float*)d_in[2];
    const float* cam_R       = (const float*)d_in[5];
    const float* cam_T       = (const float*)d_in[6];
    const float* cam_f       = (const float*)d_in[7];
    const float* cam_c       = (const float*)d_in[8];
    const float* image_wh    = (const float*)d_in[9];
    const int*   num_persons = (const int*)d_in[10];
    const float* Wr1         = (const float*)d_in[11];
    const float* br1         = (const float*)d_in[12];
    const float* Wr2         = (const float*)d_in[13];
    const float* br2         = (const float*)d_in[14];
    const float* Wc1         = (const float*)d_in[15];
    const float* bc1         = (const float*)d_in[16];
    const float* Wc2         = (const float*)d_in[17];
    const float* bc2         = (const float*)d_in[18];
    const int*   bones       = (const int*)d_in[19];
    float* out = (float*)d_out;

    cudaFuncSetAttribute(k_conv_tc, cudaFuncAttributeMaxDynamicSharedMemorySize,
                         SMEM_DYN);

    k_repack_frag<<<NMT, 256>>>(Wc1, bc1, Wc2);
    k_match<<<NROWS, 128>>>(kpts, joint_vis, cam_R, cam_T, cam_f, cam_c,
                            image_wh, num_persons, bones, Wr1, br1, Wr2, br2);
    k_conv_tc<<<NROWS, 256, SMEM_DYN>>>(bc2, out);
}